// round 12
// baseline (speedup 1.0000x reference)
#include <cuda_runtime.h>
#include <cuda_fp16.h>
#include <math.h>
#include <stdint.h>

#define NN 100000
#define FF 128
#define HH 64
#define CC 16
#define EE 1000000
#define NB 782   // ceil(NN/128)

// word strides (uint32 units), all ≡ 4 (mod 32) for conflict-free lane maps
#define WP128 68   // K=128 fp16 operand row (128 halves + pad)
#define WP64  36   // K=64 fp16 operand row
#define WGH  100   // ghh prefetch row (192 halves + pad)
#define WH0   36   // h0 prefetch row (64 halves + pad)

// ---------------- scratch ----------------------------------------------------
__device__ __align__(16) __half g_h0h[NN * HH];
__device__ __align__(16) __half g_xmidh[NN * HH];
__device__ __align__(16) __half g_ghhh[NN * 192];
__device__ __align__(16) float  g_x1[NN * HH];
__device__ __align__(16) float  g_x2[NN * HH];
__device__ __align__(16) float  g_y1[NN * HH];
__device__ __align__(16) float  g_y2[NN * HH];

// ---------------- helpers -----------------------------------------------------
__device__ __forceinline__ uint32_t f2h2(float a, float b) {
    __half2 h = __floats2half2_rn(a, b);
    return *(uint32_t*)&h;
}
__device__ __forceinline__ float2 h2f2(uint32_t u) {
    return __half22float2(*(__half2*)&u);
}
__device__ __forceinline__ void mma16(float4& d, uint32_t a0, uint32_t a1,
                                      uint32_t a2, uint32_t a3,
                                      uint32_t b0, uint32_t b1) {
    asm volatile(
        "mma.sync.aligned.m16n8k16.row.col.f32.f16.f16.f32 "
        "{%0,%1,%2,%3},{%4,%5,%6,%7},{%8,%9},{%0,%1,%2,%3};"
        : "+f"(d.x), "+f"(d.y), "+f"(d.z), "+f"(d.w)
        : "r"(a0), "r"(a1), "r"(a2), "r"(a3), "r"(b0), "r"(b1));
}
__device__ __forceinline__ float sigf(float x) {
    return 1.f / (1.f + __expf(-x));
}
__device__ __forceinline__ uint32_t smem_u32(const void* p) {
    uint32_t a;
    asm("{ .reg .u64 t; cvta.to.shared.u64 t, %1; cvt.u32.u64 %0, t; }"
        : "=r"(a) : "l"(p));
    return a;
}
#define CP_ASYNC16(dst, src) \
    asm volatile("cp.async.cg.shared.global [%0], [%1], 16;" \
                 :: "r"(dst), "l"(src) : "memory")
#define CP_COMMIT() asm volatile("cp.async.commit_group;" ::: "memory")
#define CP_WAIT0()  asm volatile("cp.async.wait_group 0;" ::: "memory")

// ---------------- zero all four scatter buffers ------------------------------
__global__ void k_zero4() {
    const int tot = NN * HH / 4;
    float4 z = make_float4(0.f, 0.f, 0.f, 0.f);
    for (int i = blockIdx.x * blockDim.x + threadIdx.x; i < tot;
         i += gridDim.x * blockDim.x) {
        reinterpret_cast<float4*>(g_x1)[i] = z;
        reinterpret_cast<float4*>(g_x2)[i] = z;
        reinterpret_cast<float4*>(g_y1)[i] = z;
        reinterpret_cast<float4*>(g_y2)[i] = z;
    }
}

// ---------------- persistent k_first: h0 = x@Wf^T+bf -------------------------
#define F_A    0                          // 128 x WP128
#define F_WF   (F_A + 128 * WP128)        // 64 x WP128
#define F_WORDS (F_WF + 64 * WP128)

__global__ __launch_bounds__(1024, 1) void k_first(const float* __restrict__ x,
                                                   const float* __restrict__ Wf,
                                                   const float* __restrict__ bf) {
    extern __shared__ uint32_t sm[];
    uint32_t* sA  = sm + F_A;
    uint32_t* sWf = sm + F_WF;
    __shared__ float sbf[64];
    int t = threadIdx.x;

    for (int i = t; i < 64 * 32; i += 1024) {
        int o = i >> 5, q = i & 31;
        float4 v = *(const float4*)(Wf + o * FF + q * 4);
        sWf[o * WP128 + q * 2]     = f2h2(v.x, v.y);
        sWf[o * WP128 + q * 2 + 1] = f2h2(v.z, v.w);
    }
    if (t < 64) sbf[t] = bf[t];
    __syncthreads();

    int w = t >> 5, lane = t & 31, g = lane >> 2, tig = lane & 3;
    int r0 = (w & 7) * 16, cw = w >> 3;

    for (int tile = blockIdx.x; tile < NB; tile += gridDim.x) {
        int base = tile * 128;
        for (int i = t; i < 128 * 32; i += 1024) {
            int node = i >> 5, q = i & 31;
            float4 v = make_float4(0.f, 0.f, 0.f, 0.f);
            if (base + node < NN)
                v = *(const float4*)(x + (base + node) * FF + q * 4);
            sA[node * WP128 + q * 2]     = f2h2(v.x, v.y);
            sA[node * WP128 + q * 2 + 1] = f2h2(v.z, v.w);
        }
        __syncthreads();

        int cb = cw * 16;
        float4 acc[2] = {};
#pragma unroll
        for (int s = 0; s < 8; s++) {
            int ko = s * 8;
            uint32_t a0 = sA[(r0 + g) * WP128 + ko + tig];
            uint32_t a1 = sA[(r0 + g + 8) * WP128 + ko + tig];
            uint32_t a2 = sA[(r0 + g) * WP128 + ko + tig + 4];
            uint32_t a3 = sA[(r0 + g + 8) * WP128 + ko + tig + 4];
#pragma unroll
            for (int nt = 0; nt < 2; nt++) {
                int o = cb + nt * 8 + g;
                mma16(acc[nt], a0, a1, a2, a3,
                      sWf[o * WP128 + ko + tig], sWf[o * WP128 + ko + tig + 4]);
            }
        }
#pragma unroll
        for (int nt = 0; nt < 2; nt++) {
            int c = cb + nt * 8 + tig * 2;
            int n1 = base + r0 + g, n2 = n1 + 8;
            if (n1 < NN)
                *(uint32_t*)(g_h0h + n1 * HH + c) =
                    f2h2(acc[nt].x + sbf[c], acc[nt].y + sbf[c + 1]);
            if (n2 < NN)
                *(uint32_t*)(g_h0h + n2 * HH + c) =
                    f2h2(acc[nt].z + sbf[c], acc[nt].w + sbf[c + 1]);
        }
        __syncthreads();
    }
}

// ---------------- persistent k_ghh: ghh = h0 @ Whh^T + bhh -------------------
// Runs concurrently with prop1 (fork stream). h0 tile cp.async'd straight in.
#define GH_W   0                          // 192 x WP64
#define GH_H   (GH_W + 192 * WP64)        // 128 x WP64
#define GH_WORDS (GH_H + 128 * WP64)

__global__ __launch_bounds__(1024, 1) void k_ghh(const float* __restrict__ Whh,
                                                 const float* __restrict__ bhh) {
    extern __shared__ uint32_t sm[];
    uint32_t* sW = sm + GH_W;
    uint32_t* sH = sm + GH_H;
    __shared__ float sbhh[192];
    int t = threadIdx.x;
    uint32_t sH_b = smem_u32(sH);

    for (int i = t; i < 192 * 16; i += 1024) {
        int o = i >> 4, q = i & 15;
        float4 v = *(const float4*)(Whh + o * HH + q * 4);
        sW[o * WP64 + q * 2]     = f2h2(v.x, v.y);
        sW[o * WP64 + q * 2 + 1] = f2h2(v.z, v.w);
    }
    if (t < 192) sbhh[t] = bhh[t];
    __syncthreads();

    int w = t >> 5, lane = t & 31, g = lane >> 2, tig = lane & 3;
    int r0 = (w & 7) * 16, cw = w >> 3;

    for (int tile = blockIdx.x; tile < NB; tile += gridDim.x) {
        int base = tile * 128;
        // cp.async the fp16 h0 tile (128 rows x 8 chunks of 16B)
        for (int i = t; i < 128 * 8; i += 1024) {
            int row = i >> 3, ch = i & 7;
            int n = base + row;
            if (n < NN)
                CP_ASYNC16(sH_b + (row * WP64 + ch * 4) * 4,
                           (const char*)(g_h0h + n * HH) + ch * 16);
        }
        CP_COMMIT();
        CP_WAIT0();
        __syncthreads();

        int cb = cw * 48;
        float4 acc[6] = {};
#pragma unroll
        for (int s = 0; s < 4; s++) {
            int ko = s * 8;
            uint32_t a0 = sH[(r0 + g) * WP64 + ko + tig];
            uint32_t a1 = sH[(r0 + g + 8) * WP64 + ko + tig];
            uint32_t a2 = sH[(r0 + g) * WP64 + ko + tig + 4];
            uint32_t a3 = sH[(r0 + g + 8) * WP64 + ko + tig + 4];
#pragma unroll
            for (int nt = 0; nt < 6; nt++) {
                int o = cb + nt * 8 + g;
                mma16(acc[nt], a0, a1, a2, a3,
                      sW[o * WP64 + ko + tig], sW[o * WP64 + ko + tig + 4]);
            }
        }
#pragma unroll
        for (int nt = 0; nt < 6; nt++) {
            int c = cb + nt * 8 + tig * 2;
            int n1 = base + r0 + g, n2 = n1 + 8;
            if (n1 < NN)
                *(uint32_t*)(g_ghhh + n1 * 192 + c) =
                    f2h2(acc[nt].x + sbhh[c], acc[nt].y + sbhh[c + 1]);
            if (n2 < NN)
                *(uint32_t*)(g_ghhh + n2 * 192 + c) =
                    f2h2(acc[nt].z + sbhh[c], acc[nt].w + sbhh[c + 1]);
        }
        __syncthreads();
    }
}

// ---------------- edge propagation: 16 lanes/edge, 4 edges/group -------------
__global__ __launch_bounds__(256) void k_prop(int use_mid,
                                              const int* __restrict__ ei1,
                                              const float* __restrict__ ew1,
                                              const int* __restrict__ ei2,
                                              const float* __restrict__ ew2) {
    const __half* xin = use_mid ? g_xmidh : g_h0h;
    int group = blockIdx.x * 16 + (threadIdx.x >> 4);
    int l16 = threadIdx.x & 15;
    int slot0 = group * 4;   // quad; never straddles EE (EE % 4 == 0)

    const int* ei;
    const float* ew;
    float* out;
    int e0;
    if (slot0 < EE) {
        e0 = slot0; ei = ei1; ew = ew1;
        out = use_mid ? g_y1 : g_x1;
    } else {
        e0 = slot0 - EE; ei = ei2; ew = ew2;
        out = use_mid ? g_y2 : g_x2;
    }

    int4   sp = *(const int4*)(ei + e0);        // 4 srcs
    int4   dp = *(const int4*)(ei + EE + e0);   // 4 dsts
    float4 wp = *(const float4*)(ew + e0);      // 4 weights

    const __half2* p0 = (const __half2*)(xin + sp.x * HH + l16 * 4);
    const __half2* p1 = (const __half2*)(xin + sp.y * HH + l16 * 4);
    const __half2* p2 = (const __half2*)(xin + sp.z * HH + l16 * 4);
    const __half2* p3 = (const __half2*)(xin + sp.w * HH + l16 * 4);
    __half2 a0 = p0[0], a1 = p0[1];
    __half2 b0 = p1[0], b1 = p1[1];
    __half2 c0 = p2[0], c1 = p2[1];
    __half2 d0 = p3[0], d1 = p3[1];

    float2 fa0 = __half22float2(a0), fa1 = __half22float2(a1);
    float2 fb0 = __half22float2(b0), fb1 = __half22float2(b1);
    float2 fc0 = __half22float2(c0), fc1 = __half22float2(c1);
    float2 fd0 = __half22float2(d0), fd1 = __half22float2(d1);

    float* q0 = out + dp.x * HH + l16 * 4;
    float* q1 = out + dp.y * HH + l16 * 4;
    float* q2 = out + dp.z * HH + l16 * 4;
    float* q3 = out + dp.w * HH + l16 * 4;
    asm volatile("red.global.add.v4.f32 [%0], {%1, %2, %3, %4};"
                 :: "l"(q0), "f"(fa0.x * wp.x), "f"(fa0.y * wp.x),
                    "f"(fa1.x * wp.x), "f"(fa1.y * wp.x) : "memory");
    asm volatile("red.global.add.v4.f32 [%0], {%1, %2, %3, %4};"
                 :: "l"(q1), "f"(fb0.x * wp.y), "f"(fb0.y * wp.y),
                    "f"(fb1.x * wp.y), "f"(fb1.y * wp.y) : "memory");
    asm volatile("red.global.add.v4.f32 [%0], {%1, %2, %3, %4};"
                 :: "l"(q2), "f"(fc0.x * wp.z), "f"(fc0.y * wp.z),
                    "f"(fc1.x * wp.z), "f"(fc1.y * wp.z) : "memory");
    asm volatile("red.global.add.v4.f32 [%0], {%1, %2, %3, %4};"
                 :: "l"(q3), "f"(fd0.x * wp.w), "f"(fd0.y * wp.w),
                    "f"(fd1.x * wp.w), "f"(fd1.y * wp.w) : "memory");
}

// ---------------- persistent fused concat-linear + GRU + out ----------------
#define O_A    0                           // 128 x WP128 (concat, fp16)
#define O_WC   (O_A + 128 * WP128)         // 64 x WP128
#define O_WIH  (O_WC + 64 * WP128)         // 192 x WP64
#define O_WL   (O_WIH + 192 * WP64)        // 64 x WP64
#define O_G    (O_WL + 64 * WP64)          // 128 x WP64 (gg / hnew, fp16)
#define O_GH   (O_G + 128 * WP64)          // 128 x WGH  (ghh prefetch)
#define O_H0   (O_GH + 128 * WGH)          // 128 x WH0  (h0 prefetch)
#define O_BC   (O_H0 + 128 * WH0)
#define O_BIH  (O_BC + 64)
#define O_BL   (O_BIH + 192)
#define O_LY   (O_BL + 64)
#define CG_WORDS (O_LY + 128 * 17)

template <bool FINAL>
__global__ __launch_bounds__(1024, 1) void k_congru(
    const float* __restrict__ Wc,  const float* __restrict__ bc,
    const float* __restrict__ Wih, const float* __restrict__ bih,
    const float* __restrict__ Wl,  const float* __restrict__ bl,
    float* __restrict__ dout) {
    extern __shared__ uint32_t sm[];
    uint32_t* sA   = sm + O_A;
    uint32_t* sWc  = sm + O_WC;
    uint32_t* sWih = sm + O_WIH;
    uint32_t* sWl  = sm + O_WL;
    uint32_t* sG   = sm + O_G;
    uint32_t* sGH  = sm + O_GH;
    uint32_t* sH0  = sm + O_H0;
    float* sbc  = (float*)(sm + O_BC);
    float* sbih = (float*)(sm + O_BIH);
    float* sbl  = (float*)(sm + O_BL);
    float* sLY  = (float*)(sm + O_LY);
    const int OC = FINAL ? CC : HH;
    const float* bx1 = FINAL ? g_y1 : g_x1;
    const float* bx2 = FINAL ? g_y2 : g_x2;

    int t = threadIdx.x;
    uint32_t sGH_b = smem_u32(sGH);
    uint32_t sH0_b = smem_u32(sH0);

    // stage weights ONCE (fp16)
    for (int i = t; i < 64 * 32; i += 1024) {
        int o = i >> 5, q = i & 31;
        float4 v = *(const float4*)(Wc + o * FF + q * 4);
        sWc[o * WP128 + q * 2]     = f2h2(v.x, v.y);
        sWc[o * WP128 + q * 2 + 1] = f2h2(v.z, v.w);
    }
    for (int i = t; i < 192 * 16; i += 1024) {
        int o = i >> 4, q = i & 15;
        float4 v = *(const float4*)(Wih + o * HH + q * 4);
        sWih[o * WP64 + q * 2]     = f2h2(v.x, v.y);
        sWih[o * WP64 + q * 2 + 1] = f2h2(v.z, v.w);
    }
    for (int i = t; i < OC * 16; i += 1024) {
        int o = i >> 4, q = i & 15;
        float4 v = *(const float4*)(Wl + o * HH + q * 4);
        sWl[o * WP64 + q * 2]     = f2h2(v.x, v.y);
        sWl[o * WP64 + q * 2 + 1] = f2h2(v.z, v.w);
    }
    if (t < 64)  sbc[t]  = bc[t];
    if (t < 192) sbih[t] = bih[t];
    if (t < OC)  sbl[t]  = bl[t];
    __syncthreads();

    int w = t >> 5, lane = t & 31, g = lane >> 2, tig = lane & 3;
    int r0 = (w & 7) * 16, cw = w >> 3, cb = cw * 16;

    for (int tile = blockIdx.x; tile < NB; tile += gridDim.x) {
        int base = tile * 128;
        for (int i = t; i < 128 * 16; i += 1024) {
            int node = i >> 4, q = i & 15;
            int n = base + node;
            float4 v1 = make_float4(0.f, 0.f, 0.f, 0.f), v2 = v1;
            if (n < NN) {
                v1 = *(const float4*)(bx1 + n * HH + q * 4);
                v2 = *(const float4*)(bx2 + n * HH + q * 4);
            }
            sA[node * WP128 + q * 2]          = f2h2(v1.x, v1.y);
            sA[node * WP128 + q * 2 + 1]      = f2h2(v1.z, v1.w);
            sA[node * WP128 + 32 + q * 2]     = f2h2(v2.x, v2.y);
            sA[node * WP128 + 32 + q * 2 + 1] = f2h2(v2.z, v2.w);
        }
        // ghh: 128 rows x 24 chunks of 16B
        for (int i = t; i < 128 * 24; i += 1024) {
            int row = i / 24, ch = i % 24;
            int n = base + row;
            if (n < NN)
                CP_ASYNC16(sGH_b + (row * WGH + ch * 4) * 4,
                           (const char*)(g_ghhh + n * 192) + ch * 16);
        }
        // h0: 128 rows x 8 chunks of 16B
        for (int i = t; i < 128 * 8; i += 1024) {
            int row = i >> 3, ch = i & 7;
            int n = base + row;
            if (n < NN)
                CP_ASYNC16(sH0_b + (row * WH0 + ch * 4) * 4,
                           (const char*)(g_h0h + n * HH) + ch * 16);
        }
        CP_COMMIT();
        __syncthreads();

        // phase 1: gg = [x1|x2] @ Wc^T + bc  (K=128, 8 k16 steps)
        {
            float4 acc[2] = {};
#pragma unroll
            for (int s = 0; s < 8; s++) {
                int ko = s * 8;
                uint32_t a0 = sA[(r0 + g) * WP128 + ko + tig];
                uint32_t a1 = sA[(r0 + g + 8) * WP128 + ko + tig];
                uint32_t a2 = sA[(r0 + g) * WP128 + ko + tig + 4];
                uint32_t a3 = sA[(r0 + g + 8) * WP128 + ko + tig + 4];
#pragma unroll
                for (int nt = 0; nt < 2; nt++) {
                    int o = cb + nt * 8 + g;
                    mma16(acc[nt], a0, a1, a2, a3,
                          sWc[o * WP128 + ko + tig], sWc[o * WP128 + ko + tig + 4]);
                }
            }
#pragma unroll
            for (int nt = 0; nt < 2; nt++) {
                int c = cb + nt * 8 + tig * 2;
                int cwd = c >> 1;
                sG[(r0 + g) * WP64 + cwd] =
                    f2h2(acc[nt].x + sbc[c], acc[nt].y + sbc[c + 1]);
                sG[(r0 + g + 8) * WP64 + cwd] =
                    f2h2(acc[nt].z + sbc[c], acc[nt].w + sbc[c + 1]);
            }
        }
        __syncthreads();

        // phase 2: gi = gg @ Wih^T  (K=64, 4 k16 steps, 3 gates x 2 nt)
        float4 d2[3][2];
#pragma unroll
        for (int gt = 0; gt < 3; gt++)
#pragma unroll
            for (int nt = 0; nt < 2; nt++)
                d2[gt][nt] = make_float4(0.f, 0.f, 0.f, 0.f);
#pragma unroll
        for (int s = 0; s < 4; s++) {
            int ko = s * 8;
            uint32_t a0 = sG[(r0 + g) * WP64 + ko + tig];
            uint32_t a1 = sG[(r0 + g + 8) * WP64 + ko + tig];
            uint32_t a2 = sG[(r0 + g) * WP64 + ko + tig + 4];
            uint32_t a3 = sG[(r0 + g + 8) * WP64 + ko + tig + 4];
#pragma unroll
            for (int gt = 0; gt < 3; gt++)
#pragma unroll
                for (int nt = 0; nt < 2; nt++) {
                    int o = gt * 64 + cb + nt * 8 + g;
                    mma16(d2[gt][nt], a0, a1, a2, a3,
                          sWih[o * WP64 + ko + tig], sWih[o * WP64 + ko + tig + 4]);
                }
        }

        CP_WAIT0();
        __syncthreads();

        // phase 3: GRU elementwise (from prefetched smem)
        float hn[2][4];
#pragma unroll
        for (int nt = 0; nt < 2; nt++) {
            int c = cb + nt * 8 + tig * 2;
            int cwd = c >> 1;
#pragma unroll
            for (int half = 0; half < 2; half++) {
                int nl = r0 + g + half * 8;
                float vr0 = half ? d2[0][nt].z : d2[0][nt].x;
                float vr1 = half ? d2[0][nt].w : d2[0][nt].y;
                float vz0 = half ? d2[1][nt].z : d2[1][nt].x;
                float vz1 = half ? d2[1][nt].w : d2[1][nt].y;
                float vn0 = half ? d2[2][nt].z : d2[2][nt].x;
                float vn1 = half ? d2[2][nt].w : d2[2][nt].y;
                float2 gr = h2f2(sGH[nl * WGH + cwd]);
                float2 gz = h2f2(sGH[nl * WGH + 32 + cwd]);
                float2 gn = h2f2(sGH[nl * WGH + 64 + cwd]);
                float2 h  = h2f2(sH0[nl * WH0 + cwd]);
                float r = sigf(vr0 + sbih[c] + gr.x);
                float z = sigf(vz0 + sbih[64 + c] + gz.x);
                float n = tanhf(vn0 + sbih[128 + c] + r * gn.x);
                hn[nt][half * 2] = (1.f - z) * n + z * h.x;
                r = sigf(vr1 + sbih[c + 1] + gr.y);
                z = sigf(vz1 + sbih[64 + c + 1] + gz.y);
                n = tanhf(vn1 + sbih[128 + c + 1] + r * gn.y);
                hn[nt][half * 2 + 1] = (1.f - z) * n + z * h.y;
            }
        }
        __syncthreads();
#pragma unroll
        for (int nt = 0; nt < 2; nt++) {
            int c = cb + nt * 8 + tig * 2;
            int cwd = c >> 1;
            sG[(r0 + g) * WP64 + cwd]     = f2h2(hn[nt][0], hn[nt][1]);
            sG[(r0 + g + 8) * WP64 + cwd] = f2h2(hn[nt][2], hn[nt][3]);
        }
        __syncthreads();

        // phase 4: output GEMM (K=64, 4 k16 steps)
        if (!FINAL) {
            float4 acc[2] = {};
#pragma unroll
            for (int s = 0; s < 4; s++) {
                int ko = s * 8;
                uint32_t a0 = sG[(r0 + g) * WP64 + ko + tig];
                uint32_t a1 = sG[(r0 + g + 8) * WP64 + ko + tig];
                uint32_t a2 = sG[(r0 + g) * WP64 + ko + tig + 4];
                uint32_t a3 = sG[(r0 + g + 8) * WP64 + ko + tig + 4];
#pragma unroll
                for (int nt = 0; nt < 2; nt++) {
                    int o = cb + nt * 8 + g;
                    mma16(acc[nt], a0, a1, a2, a3,
                          sWl[o * WP64 + ko + tig], sWl[o * WP64 + ko + tig + 4]);
                }
            }
#pragma unroll
            for (int nt = 0; nt < 2; nt++) {
                int c = cb + nt * 8 + tig * 2;
                int n1 = base + r0 + g, n2 = n1 + 8;
                if (n1 < NN)
                    *(uint32_t*)(g_xmidh + n1 * HH + c) =
                        f2h2(acc[nt].x + sbl[c], acc[nt].y + sbl[c + 1]);
                if (n2 < NN)
                    *(uint32_t*)(g_xmidh + n2 * HH + c) =
                        f2h2(acc[nt].z + sbl[c], acc[nt].w + sbl[c + 1]);
            }
        } else {
            if (cw < 2) {
                float4 acc = make_float4(0.f, 0.f, 0.f, 0.f);
                int c0f = cw * 8;
#pragma unroll
                for (int s = 0; s < 4; s++) {
                    int ko = s * 8;
                    uint32_t a0 = sG[(r0 + g) * WP64 + ko + tig];
                    uint32_t a1 = sG[(r0 + g + 8) * WP64 + ko + tig];
                    uint32_t a2 = sG[(r0 + g) * WP64 + ko + tig + 4];
                    uint32_t a3 = sG[(r0 + g + 8) * WP64 + ko + tig + 4];
                    int o = c0f + g;
                    mma16(acc, a0, a1, a2, a3,
                          sWl[o * WP64 + ko + tig], sWl[o * WP64 + ko + tig + 4]);
                }
                int c = c0f + tig * 2;
                sLY[(r0 + g) * 17 + c]         = acc.x + sbl[c];
                sLY[(r0 + g) * 17 + c + 1]     = acc.y + sbl[c + 1];
                sLY[(r0 + g + 8) * 17 + c]     = acc.z + sbl[c];
                sLY[(r0 + g + 8) * 17 + c + 1] = acc.w + sbl[c + 1];
            }
            __syncthreads();
            if (t < 128) {
                int node = base + t;
                if (node < NN) {
                    float m = -1e30f;
#pragma unroll
                    for (int cc = 0; cc < 16; cc++) m = fmaxf(m, sLY[t * 17 + cc]);
                    float s = 0.f;
#pragma unroll
                    for (int cc = 0; cc < 16; cc++) s += expf(sLY[t * 17 + cc] - m);
                    float l = m + logf(s);
#pragma unroll
                    for (int cc = 0; cc < 16; cc++)
                        dout[node * CC + cc] = sLY[t * 17 + cc] - l;
                }
            }
        }
        __syncthreads();
    }
}

// ---------------- launch -----------------------------------------------------
extern "C" void kernel_launch(void* const* d_in, const int* in_sizes, int n_in,
                              void* d_out, int out_size) {
    const float* x       = (const float*)d_in[0];
    const int*   ei      = (const int*)  d_in[1];
    const float* ew      = (const float*)d_in[2];
    const int*   eir     = (const int*)  d_in[3];
    const float* ewr     = (const float*)d_in[4];
    const float* W_first = (const float*)d_in[5];
    const float* b_first = (const float*)d_in[6];
    const float* W_con1  = (const float*)d_in[7];
    const float* b_con1  = (const float*)d_in[8];
    const float* W_con2  = (const float*)d_in[9];
    const float* b_con2  = (const float*)d_in[10];
    const float* W_lin1  = (const float*)d_in[11];
    const float* b_lin1  = (const float*)d_in[12];
    const float* W_out   = (const float*)d_in[13];
    const float* b_out   = (const float*)d_in[14];
    const float* W_ih    = (const float*)d_in[15];
    const float* W_hh    = (const float*)d_in[16];
    const float* b_ih    = (const float*)d_in[17];
    const float* b_hh    = (const float*)d_in[18];
    float* out = (float*)d_out;

    const int SM_F  = F_WORDS * 4;
    const int SM_GH = GH_WORDS * 4;
    const int SM_CG = CG_WORDS * 4;

    static cudaStream_t s1 = nullptr;
    static cudaEvent_t evFork = nullptr, evF = nullptr, evZ = nullptr, evG = nullptr;
    if (!s1) {
        cudaStreamCreateWithFlags(&s1, cudaStreamNonBlocking);
        cudaEventCreateWithFlags(&evFork, cudaEventDisableTiming);
        cudaEventCreateWithFlags(&evF, cudaEventDisableTiming);
        cudaEventCreateWithFlags(&evZ, cudaEventDisableTiming);
        cudaEventCreateWithFlags(&evG, cudaEventDisableTiming);
        cudaFuncSetAttribute(k_first,
                             cudaFuncAttributeMaxDynamicSharedMemorySize, SM_F);
        cudaFuncSetAttribute(k_ghh,
                             cudaFuncAttributeMaxDynamicSharedMemorySize, SM_GH);
        cudaFuncSetAttribute(k_congru<false>,
                             cudaFuncAttributeMaxDynamicSharedMemorySize, SM_CG);
        cudaFuncSetAttribute(k_congru<true>,
                             cudaFuncAttributeMaxDynamicSharedMemorySize, SM_CG);
    }

    const int PERS = 148;
    const int PROP_BLOCKS = (2 * EE) / 64;   // 4 edges per 16-lane group

    // fork: s1 runs zero4 (independent of k_first)
    cudaEventRecord(evFork, 0);
    cudaStreamWaitEvent(s1, evFork, 0);
    k_zero4<<<1024, 256, 0, s1>>>();
    cudaEventRecord(evZ, s1);

    k_first<<<PERS, 1024, SM_F>>>(x, W_first, b_first);
    cudaEventRecord(evF, 0);

    // s1: ghh after k_first (needs h0h), concurrent with prop1
    cudaStreamWaitEvent(s1, evF, 0);
    k_ghh<<<PERS, 1024, SM_GH, s1>>>(W_hh, b_hh);
    cudaEventRecord(evG, s1);

    // main stream: prop1 after zero4 (+ k_first by stream order)
    cudaStreamWaitEvent(0, evZ, 0);
    k_prop<<<PROP_BLOCKS, 256>>>(0, ei, ew, eir, ewr);

    // congru0 needs ghh done (join fork back into main stream)
    cudaStreamWaitEvent(0, evG, 0);
    k_congru<false><<<PERS, 1024, SM_CG>>>(W_con1, b_con1, W_ih, b_ih,
                                           W_lin1, b_lin1, nullptr);
    k_prop<<<PROP_BLOCKS, 256>>>(1, ei, ew, eir, ewr);
    k_congru<true><<<PERS, 1024, SM_CG>>>(W_con2, b_con2, W_ih, b_ih,
                                          W_out, b_out, out);
}

// round 13
// speedup vs baseline: 1.2155x; 1.2155x over previous
#include <cuda_runtime.h>
#include <cuda_fp16.h>
#include <math.h>
#include <stdint.h>

#define NN 100000
#define FF 128
#define HH 64
#define CC 16
#define EE 1000000
#define NB 782   // ceil(NN/128)
#define NCH 98   // ceil(NN/1024)
#define CHK 1024

// word strides (uint32 units), all ≡ 4 (mod 32) for conflict-free lane maps
#define WP128 68
#define WP64  36
#define WGH  100
#define WH0   36

// ---------------- scratch ----------------------------------------------------
__device__ __align__(16) __half g_h0h[NN * HH];
__device__ __align__(16) __half g_xmidh[NN * HH];
__device__ __align__(16) __half g_ghhh[NN * 192];
__device__ __align__(16) float  g_x1[NN * HH];
__device__ __align__(16) float  g_x2[NN * HH];

// CSR build scratch
__device__ int g_cnt1[NN], g_cnt2[NN];
__device__ int g_off1[NN + 1], g_off2[NN + 1];
__device__ int g_pos1[NN], g_pos2[NN];
__device__ int g_psum[2 * NCH];
__device__ __align__(8) int2 g_se1[EE];
__device__ __align__(8) int2 g_se2[EE];

// ---------------- helpers -----------------------------------------------------
__device__ __forceinline__ uint32_t f2h2(float a, float b) {
    __half2 h = __floats2half2_rn(a, b);
    return *(uint32_t*)&h;
}
__device__ __forceinline__ float2 h2f2(uint32_t u) {
    return __half22float2(*(__half2*)&u);
}
__device__ __forceinline__ void mma16(float4& d, uint32_t a0, uint32_t a1,
                                      uint32_t a2, uint32_t a3,
                                      uint32_t b0, uint32_t b1) {
    asm volatile(
        "mma.sync.aligned.m16n8k16.row.col.f32.f16.f16.f32 "
        "{%0,%1,%2,%3},{%4,%5,%6,%7},{%8,%9},{%0,%1,%2,%3};"
        : "+f"(d.x), "+f"(d.y), "+f"(d.z), "+f"(d.w)
        : "r"(a0), "r"(a1), "r"(a2), "r"(a3), "r"(b0), "r"(b1));
}
__device__ __forceinline__ float sigf(float x) {
    return 1.f / (1.f + __expf(-x));
}
__device__ __forceinline__ uint32_t smem_u32(const void* p) {
    uint32_t a;
    asm("{ .reg .u64 t; cvta.to.shared.u64 t, %1; cvt.u32.u64 %0, t; }"
        : "=r"(a) : "l"(p));
    return a;
}
#define CP_ASYNC16(dst, src) \
    asm volatile("cp.async.cg.shared.global [%0], [%1], 16;" \
                 :: "r"(dst), "l"(src) : "memory")
#define CP_COMMIT() asm volatile("cp.async.commit_group;" ::: "memory")
#define CP_WAIT0()  asm volatile("cp.async.wait_group 0;" ::: "memory")

// ================= CSR build ==================================================
__global__ void k_zcnt() {
    int i = blockIdx.x * blockDim.x + threadIdx.x;
    if (i < NN) { g_cnt1[i] = 0; g_cnt2[i] = 0; }
}
__global__ void k_hist(const int* __restrict__ ei1,
                       const int* __restrict__ ei2) {
    int e = blockIdx.x * blockDim.x + threadIdx.x;
    if (e < EE) {
        atomicAdd(&g_cnt1[ei1[EE + e]], 1);
        atomicAdd(&g_cnt2[ei2[EE + e]], 1);
    }
}
__global__ __launch_bounds__(1024) void k_psum() {
    int b = blockIdx.x, t = threadIdx.x;
    const int* cnt = (b < NCH) ? g_cnt1 : g_cnt2;
    int ch = (b < NCH) ? b : b - NCH;
    int n = ch * CHK + t;
    int v = (n < NN) ? cnt[n] : 0;
    __shared__ int ss[1024];
    ss[t] = v; __syncthreads();
    for (int d = 512; d > 0; d >>= 1) {
        if (t < d) ss[t] += ss[t + d];
        __syncthreads();
    }
    if (t == 0) g_psum[b] = ss[0];
}
__global__ __launch_bounds__(256) void k_topscan() {
    __shared__ int s[2 * NCH];
    int t = threadIdx.x;
    if (t < 2 * NCH) s[t] = g_psum[t];
    __syncthreads();
    if (t == 0) { int a = 0; for (int i = 0; i < NCH; i++) { int v = s[i]; s[i] = a; a += v; } }
    if (t == 1) { int a = 0; for (int i = NCH; i < 2 * NCH; i++) { int v = s[i]; s[i] = a; a += v; } }
    __syncthreads();
    if (t < 2 * NCH) g_psum[t] = s[t];
}
__global__ __launch_bounds__(1024) void k_makeoff() {
    int b = blockIdx.x, t = threadIdx.x;
    bool l1 = (b < NCH);
    const int* cnt = l1 ? g_cnt1 : g_cnt2;
    int* off = l1 ? g_off1 : g_off2;
    int* pos = l1 ? g_pos1 : g_pos2;
    int ch = l1 ? b : b - NCH;
    int n = ch * CHK + t;
    int v = (n < NN) ? cnt[n] : 0;
    __shared__ int ss[1024];
    ss[t] = v; __syncthreads();
    for (int d = 1; d < 1024; d <<= 1) {
        int x = (t >= d) ? ss[t - d] : 0;
        __syncthreads();
        ss[t] += x;
        __syncthreads();
    }
    int excl = ss[t] - v + g_psum[b];
    if (n < NN) { off[n] = excl; pos[n] = excl; }
    if (t == 0 && ch == NCH - 1) off[NN] = EE;
}
__global__ void k_scatter(const int* __restrict__ ei1,
                          const float* __restrict__ ew1,
                          const int* __restrict__ ei2,
                          const float* __restrict__ ew2) {
    int e = blockIdx.x * blockDim.x + threadIdx.x;
    if (e < EE) {
        int d1 = ei1[EE + e];
        int p1 = atomicAdd(&g_pos1[d1], 1);
        g_se1[p1] = make_int2(ei1[e], __float_as_int(ew1[e]));
        int d2 = ei2[EE + e];
        int p2 = atomicAdd(&g_pos2[d2], 1);
        g_se2[p2] = make_int2(ei2[e], __float_as_int(ew2[e]));
    }
}

// ---------------- gather-CSR propagation: 16 lanes per dst node --------------
__global__ __launch_bounds__(256) void k_prop_csr(int use_mid) {
    const __half* xin = use_mid ? g_xmidh : g_h0h;
    int gi = blockIdx.x * 16 + (threadIdx.x >> 4);
    int l16 = threadIdx.x & 15;

    const int* off; const int2* se; float* out; int node;
    if (gi < NN) { node = gi;      off = g_off1; se = g_se1; out = g_x1; }
    else         { node = gi - NN; off = g_off2; se = g_se2; out = g_x2; }

    int beg = off[node], end = off[node + 1];
    float4 acc = make_float4(0.f, 0.f, 0.f, 0.f);
    int e = beg;
    for (; e + 1 < end; e += 2) {
        int2 e0 = __ldg(&se[e]);
        int2 e1 = __ldg(&se[e + 1]);
        float w0 = __int_as_float(e0.y), w1 = __int_as_float(e1.y);
        uint2 u0 = *(const uint2*)(xin + e0.x * HH + l16 * 4);
        uint2 u1 = *(const uint2*)(xin + e1.x * HH + l16 * 4);
        float2 a0 = h2f2(u0.x), a1 = h2f2(u0.y);
        float2 b0 = h2f2(u1.x), b1 = h2f2(u1.y);
        acc.x += a0.x * w0 + b0.x * w1;
        acc.y += a0.y * w0 + b0.y * w1;
        acc.z += a1.x * w0 + b1.x * w1;
        acc.w += a1.y * w0 + b1.y * w1;
    }
    if (e < end) {
        int2 e0 = __ldg(&se[e]);
        float w0 = __int_as_float(e0.y);
        uint2 u0 = *(const uint2*)(xin + e0.x * HH + l16 * 4);
        float2 a0 = h2f2(u0.x), a1 = h2f2(u0.y);
        acc.x += a0.x * w0; acc.y += a0.y * w0;
        acc.z += a1.x * w0; acc.w += a1.y * w0;
    }
    *(float4*)(out + node * HH + l16 * 4) = acc;
}

// ---------------- persistent k_first: h0 = x@Wf^T+bf -------------------------
#define F_A    0
#define F_WF   (F_A + 128 * WP128)
#define F_WORDS (F_WF + 64 * WP128)

__global__ __launch_bounds__(1024, 1) void k_first(const float* __restrict__ x,
                                                   const float* __restrict__ Wf,
                                                   const float* __restrict__ bf) {
    extern __shared__ uint32_t sm[];
    uint32_t* sA  = sm + F_A;
    uint32_t* sWf = sm + F_WF;
    __shared__ float sbf[64];
    int t = threadIdx.x;

    for (int i = t; i < 64 * 32; i += 1024) {
        int o = i >> 5, q = i & 31;
        float4 v = *(const float4*)(Wf + o * FF + q * 4);
        sWf[o * WP128 + q * 2]     = f2h2(v.x, v.y);
        sWf[o * WP128 + q * 2 + 1] = f2h2(v.z, v.w);
    }
    if (t < 64) sbf[t] = bf[t];
    __syncthreads();

    int w = t >> 5, lane = t & 31, g = lane >> 2, tig = lane & 3;
    int r0 = (w & 7) * 16, cw = w >> 3;

    for (int tile = blockIdx.x; tile < NB; tile += gridDim.x) {
        int base = tile * 128;
        for (int i = t; i < 128 * 32; i += 1024) {
            int node = i >> 5, q = i & 31;
            float4 v = make_float4(0.f, 0.f, 0.f, 0.f);
            if (base + node < NN)
                v = *(const float4*)(x + (base + node) * FF + q * 4);
            sA[node * WP128 + q * 2]     = f2h2(v.x, v.y);
            sA[node * WP128 + q * 2 + 1] = f2h2(v.z, v.w);
        }
        __syncthreads();

        int cb = cw * 16;
        float4 acc[2] = {};
#pragma unroll
        for (int s = 0; s < 8; s++) {
            int ko = s * 8;
            uint32_t a0 = sA[(r0 + g) * WP128 + ko + tig];
            uint32_t a1 = sA[(r0 + g + 8) * WP128 + ko + tig];
            uint32_t a2 = sA[(r0 + g) * WP128 + ko + tig + 4];
            uint32_t a3 = sA[(r0 + g + 8) * WP128 + ko + tig + 4];
#pragma unroll
            for (int nt = 0; nt < 2; nt++) {
                int o = cb + nt * 8 + g;
                mma16(acc[nt], a0, a1, a2, a3,
                      sWf[o * WP128 + ko + tig], sWf[o * WP128 + ko + tig + 4]);
            }
        }
#pragma unroll
        for (int nt = 0; nt < 2; nt++) {
            int c = cb + nt * 8 + tig * 2;
            int n1 = base + r0 + g, n2 = n1 + 8;
            if (n1 < NN)
                *(uint32_t*)(g_h0h + n1 * HH + c) =
                    f2h2(acc[nt].x + sbf[c], acc[nt].y + sbf[c + 1]);
            if (n2 < NN)
                *(uint32_t*)(g_h0h + n2 * HH + c) =
                    f2h2(acc[nt].z + sbf[c], acc[nt].w + sbf[c + 1]);
        }
        __syncthreads();
    }
}

// ---------------- persistent k_ghh: ghh = h0 @ Whh^T + bhh -------------------
#define GH_W   0
#define GH_H   (GH_W + 192 * WP64)
#define GH_WORDS (GH_H + 128 * WP64)

__global__ __launch_bounds__(1024, 1) void k_ghh(const float* __restrict__ Whh,
                                                 const float* __restrict__ bhh) {
    extern __shared__ uint32_t sm[];
    uint32_t* sW = sm + GH_W;
    uint32_t* sH = sm + GH_H;
    __shared__ float sbhh[192];
    int t = threadIdx.x;
    uint32_t sH_b = smem_u32(sH);

    for (int i = t; i < 192 * 16; i += 1024) {
        int o = i >> 4, q = i & 15;
        float4 v = *(const float4*)(Whh + o * HH + q * 4);
        sW[o * WP64 + q * 2]     = f2h2(v.x, v.y);
        sW[o * WP64 + q * 2 + 1] = f2h2(v.z, v.w);
    }
    if (t < 192) sbhh[t] = bhh[t];
    __syncthreads();

    int w = t >> 5, lane = t & 31, g = lane >> 2, tig = lane & 3;
    int r0 = (w & 7) * 16, cw = w >> 3;

    for (int tile = blockIdx.x; tile < NB; tile += gridDim.x) {
        int base = tile * 128;
        for (int i = t; i < 128 * 8; i += 1024) {
            int row = i >> 3, ch = i & 7;
            int n = base + row;
            if (n < NN)
                CP_ASYNC16(sH_b + (row * WP64 + ch * 4) * 4,
                           (const char*)(g_h0h + n * HH) + ch * 16);
        }
        CP_COMMIT();
        CP_WAIT0();
        __syncthreads();

        int cb = cw * 48;
        float4 acc[6] = {};
#pragma unroll
        for (int s = 0; s < 4; s++) {
            int ko = s * 8;
            uint32_t a0 = sH[(r0 + g) * WP64 + ko + tig];
            uint32_t a1 = sH[(r0 + g + 8) * WP64 + ko + tig];
            uint32_t a2 = sH[(r0 + g) * WP64 + ko + tig + 4];
            uint32_t a3 = sH[(r0 + g + 8) * WP64 + ko + tig + 4];
#pragma unroll
            for (int nt = 0; nt < 6; nt++) {
                int o = cb + nt * 8 + g;
                mma16(acc[nt], a0, a1, a2, a3,
                      sW[o * WP64 + ko + tig], sW[o * WP64 + ko + tig + 4]);
            }
        }
#pragma unroll
        for (int nt = 0; nt < 6; nt++) {
            int c = cb + nt * 8 + tig * 2;
            int n1 = base + r0 + g, n2 = n1 + 8;
            if (n1 < NN)
                *(uint32_t*)(g_ghhh + n1 * 192 + c) =
                    f2h2(acc[nt].x + sbhh[c], acc[nt].y + sbhh[c + 1]);
            if (n2 < NN)
                *(uint32_t*)(g_ghhh + n2 * 192 + c) =
                    f2h2(acc[nt].z + sbhh[c], acc[nt].w + sbhh[c + 1]);
        }
        __syncthreads();
    }
}

// ---------------- persistent fused concat-linear + GRU + out ----------------
#define O_A    0
#define O_WC   (O_A + 128 * WP128)
#define O_WIH  (O_WC + 64 * WP128)
#define O_WL   (O_WIH + 192 * WP64)
#define O_G    (O_WL + 64 * WP64)
#define O_GH   (O_G + 128 * WP64)
#define O_H0   (O_GH + 128 * WGH)
#define O_BC   (O_H0 + 128 * WH0)
#define O_BIH  (O_BC + 64)
#define O_BL   (O_BIH + 192)
#define O_LY   (O_BL + 64)
#define CG_WORDS (O_LY + 128 * 17)

template <bool FINAL>
__global__ __launch_bounds__(1024, 1) void k_congru(
    const float* __restrict__ Wc,  const float* __restrict__ bc,
    const float* __restrict__ Wih, const float* __restrict__ bih,
    const float* __restrict__ Wl,  const float* __restrict__ bl,
    float* __restrict__ dout) {
    extern __shared__ uint32_t sm[];
    uint32_t* sA   = sm + O_A;
    uint32_t* sWc  = sm + O_WC;
    uint32_t* sWih = sm + O_WIH;
    uint32_t* sWl  = sm + O_WL;
    uint32_t* sG   = sm + O_G;
    uint32_t* sGH  = sm + O_GH;
    uint32_t* sH0  = sm + O_H0;
    float* sbc  = (float*)(sm + O_BC);
    float* sbih = (float*)(sm + O_BIH);
    float* sbl  = (float*)(sm + O_BL);
    float* sLY  = (float*)(sm + O_LY);
    const int OC = FINAL ? CC : HH;

    int t = threadIdx.x;
    uint32_t sGH_b = smem_u32(sGH);
    uint32_t sH0_b = smem_u32(sH0);

    for (int i = t; i < 64 * 32; i += 1024) {
        int o = i >> 5, q = i & 31;
        float4 v = *(const float4*)(Wc + o * FF + q * 4);
        sWc[o * WP128 + q * 2]     = f2h2(v.x, v.y);
        sWc[o * WP128 + q * 2 + 1] = f2h2(v.z, v.w);
    }
    for (int i = t; i < 192 * 16; i += 1024) {
        int o = i >> 4, q = i & 15;
        float4 v = *(const float4*)(Wih + o * HH + q * 4);
        sWih[o * WP64 + q * 2]     = f2h2(v.x, v.y);
        sWih[o * WP64 + q * 2 + 1] = f2h2(v.z, v.w);
    }
    for (int i = t; i < OC * 16; i += 1024) {
        int o = i >> 4, q = i & 15;
        float4 v = *(const float4*)(Wl + o * HH + q * 4);
        sWl[o * WP64 + q * 2]     = f2h2(v.x, v.y);
        sWl[o * WP64 + q * 2 + 1] = f2h2(v.z, v.w);
    }
    if (t < 64)  sbc[t]  = bc[t];
    if (t < 192) sbih[t] = bih[t];
    if (t < OC)  sbl[t]  = bl[t];
    __syncthreads();

    int w = t >> 5, lane = t & 31, g = lane >> 2, tig = lane & 3;
    int r0 = (w & 7) * 16, cw = w >> 3, cb = cw * 16;

    for (int tile = blockIdx.x; tile < NB; tile += gridDim.x) {
        int base = tile * 128;
        for (int i = t; i < 128 * 16; i += 1024) {
            int node = i >> 4, q = i & 15;
            int n = base + node;
            float4 v1 = make_float4(0.f, 0.f, 0.f, 0.f), v2 = v1;
            if (n < NN) {
                v1 = *(const float4*)(g_x1 + n * HH + q * 4);
                v2 = *(const float4*)(g_x2 + n * HH + q * 4);
            }
            sA[node * WP128 + q * 2]          = f2h2(v1.x, v1.y);
            sA[node * WP128 + q * 2 + 1]      = f2h2(v1.z, v1.w);
            sA[node * WP128 + 32 + q * 2]     = f2h2(v2.x, v2.y);
            sA[node * WP128 + 32 + q * 2 + 1] = f2h2(v2.z, v2.w);
        }
        for (int i = t; i < 128 * 24; i += 1024) {
            int row = i / 24, ch = i % 24;
            int n = base + row;
            if (n < NN)
                CP_ASYNC16(sGH_b + (row * WGH + ch * 4) * 4,
                           (const char*)(g_ghhh + n * 192) + ch * 16);
        }
        for (int i = t; i < 128 * 8; i += 1024) {
            int row = i >> 3, ch = i & 7;
            int n = base + row;
            if (n < NN)
                CP_ASYNC16(sH0_b + (row * WH0 + ch * 4) * 4,
                           (const char*)(g_h0h + n * HH) + ch * 16);
        }
        CP_COMMIT();
        __syncthreads();

        // phase 1
        {
            float4 acc[2] = {};
#pragma unroll
            for (int s = 0; s < 8; s++) {
                int ko = s * 8;
                uint32_t a0 = sA[(r0 + g) * WP128 + ko + tig];
                uint32_t a1 = sA[(r0 + g + 8) * WP128 + ko + tig];
                uint32_t a2 = sA[(r0 + g) * WP128 + ko + tig + 4];
                uint32_t a3 = sA[(r0 + g + 8) * WP128 + ko + tig + 4];
#pragma unroll
                for (int nt = 0; nt < 2; nt++) {
                    int o = cb + nt * 8 + g;
                    mma16(acc[nt], a0, a1, a2, a3,
                          sWc[o * WP128 + ko + tig], sWc[o * WP128 + ko + tig + 4]);
                }
            }
#pragma unroll
            for (int nt = 0; nt < 2; nt++) {
                int c = cb + nt * 8 + tig * 2;
                int cwd = c >> 1;
                sG[(r0 + g) * WP64 + cwd] =
                    f2h2(acc[nt].x + sbc[c], acc[nt].y + sbc[c + 1]);
                sG[(r0 + g + 8) * WP64 + cwd] =
                    f2h2(acc[nt].z + sbc[c], acc[nt].w + sbc[c + 1]);
            }
        }
        __syncthreads();

        // phase 2
        float4 d2[3][2];
#pragma unroll
        for (int gt = 0; gt < 3; gt++)
#pragma unroll
            for (int nt = 0; nt < 2; nt++)
                d2[gt][nt] = make_float4(0.f, 0.f, 0.f, 0.f);
#pragma unroll
        for (int s = 0; s < 4; s++) {
            int ko = s * 8;
            uint32_t a0 = sG[(r0 + g) * WP64 + ko + tig];
            uint32_t a1 = sG[(r0 + g + 8) * WP64 + ko + tig];
            uint32_t a2 = sG[(r0 + g) * WP64 + ko + tig + 4];
            uint32_t a3 = sG[(r0 + g + 8) * WP64 + ko + tig + 4];
#pragma unroll
            for (int gt = 0; gt < 3; gt++)
#pragma unroll
                for (int nt = 0; nt < 2; nt++) {
                    int o = gt * 64 + cb + nt * 8 + g;
                    mma16(d2[gt][nt], a0, a1, a2, a3,
                          sWih[o * WP64 + ko + tig], sWih[o * WP64 + ko + tig + 4]);
                }
        }

        CP_WAIT0();
        __syncthreads();

        // phase 3: GRU
        float hn[2][4];
#pragma unroll
        for (int nt = 0; nt < 2; nt++) {
            int c = cb + nt * 8 + tig * 2;
            int cwd = c >> 1;
#pragma unroll
            for (int half = 0; half < 2; half++) {
                int nl = r0 + g + half * 8;
                float vr0 = half ? d2[0][nt].z : d2[0][nt].x;
                float vr1 = half ? d2[0][nt].w : d2[0][nt].y;
                float vz0 = half ? d2[1][nt].z : d2[1][nt].x;
                float vz1 = half ? d2[1][nt].w : d2[1][nt].y;
                float vn0 = half ? d2[2][nt].z : d2[2][nt].x;
                float vn1 = half ? d2[2][nt].w : d2[2][nt].y;
                float2 gr = h2f2(sGH[nl * WGH + cwd]);
                float2 gz = h2f2(sGH[nl * WGH + 32 + cwd]);
                float2 gn = h2f2(sGH[nl * WGH + 64 + cwd]);
                float2 h  = h2f2(sH0[nl * WH0 + cwd]);
                float r = sigf(vr0 + sbih[c] + gr.x);
                float z = sigf(vz0 + sbih[64 + c] + gz.x);
                float n = tanhf(vn0 + sbih[128 + c] + r * gn.x);
                hn[nt][half * 2] = (1.f - z) * n + z * h.x;
                r = sigf(vr1 + sbih[c + 1] + gr.y);
                z = sigf(vz1 + sbih[64 + c + 1] + gz.y);
                n = tanhf(vn1 + sbih[128 + c + 1] + r * gn.y);
                hn[nt][half * 2 + 1] = (1.f - z) * n + z * h.y;
            }
        }
        __syncthreads();
#pragma unroll
        for (int nt = 0; nt < 2; nt++) {
            int c = cb + nt * 8 + tig * 2;
            int cwd = c >> 1;
            sG[(r0 + g) * WP64 + cwd]     = f2h2(hn[nt][0], hn[nt][1]);
            sG[(r0 + g + 8) * WP64 + cwd] = f2h2(hn[nt][2], hn[nt][3]);
        }
        __syncthreads();

        // phase 4
        if (!FINAL) {
            float4 acc[2] = {};
#pragma unroll
            for (int s = 0; s < 4; s++) {
                int ko = s * 8;
                uint32_t a0 = sG[(r0 + g) * WP64 + ko + tig];
                uint32_t a1 = sG[(r0 + g + 8) * WP64 + ko + tig];
                uint32_t a2 = sG[(r0 + g) * WP64 + ko + tig + 4];
                uint32_t a3 = sG[(r0 + g + 8) * WP64 + ko + tig + 4];
#pragma unroll
                for (int nt = 0; nt < 2; nt++) {
                    int o = cb + nt * 8 + g;
                    mma16(acc[nt], a0, a1, a2, a3,
                          sWl[o * WP64 + ko + tig], sWl[o * WP64 + ko + tig + 4]);
                }
            }
#pragma unroll
            for (int nt = 0; nt < 2; nt++) {
                int c = cb + nt * 8 + tig * 2;
                int n1 = base + r0 + g, n2 = n1 + 8;
                if (n1 < NN)
                    *(uint32_t*)(g_xmidh + n1 * HH + c) =
                        f2h2(acc[nt].x + sbl[c], acc[nt].y + sbl[c + 1]);
                if (n2 < NN)
                    *(uint32_t*)(g_xmidh + n2 * HH + c) =
                        f2h2(acc[nt].z + sbl[c], acc[nt].w + sbl[c + 1]);
            }
        } else {
            if (cw < 2) {
                float4 acc = make_float4(0.f, 0.f, 0.f, 0.f);
                int c0f = cw * 8;
#pragma unroll
                for (int s = 0; s < 4; s++) {
                    int ko = s * 8;
                    uint32_t a0 = sG[(r0 + g) * WP64 + ko + tig];
                    uint32_t a1 = sG[(r0 + g + 8) * WP64 + ko + tig];
                    uint32_t a2 = sG[(r0 + g) * WP64 + ko + tig + 4];
                    uint32_t a3 = sG[(r0 + g + 8) * WP64 + ko + tig + 4];
                    int o = c0f + g;
                    mma16(acc, a0, a1, a2, a3,
                          sWl[o * WP64 + ko + tig], sWl[o * WP64 + ko + tig + 4]);
                }
                int c = c0f + tig * 2;
                sLY[(r0 + g) * 17 + c]         = acc.x + sbl[c];
                sLY[(r0 + g) * 17 + c + 1]     = acc.y + sbl[c + 1];
                sLY[(r0 + g + 8) * 17 + c]     = acc.z + sbl[c];
                sLY[(r0 + g + 8) * 17 + c + 1] = acc.w + sbl[c + 1];
            }
            __syncthreads();
            if (t < 128) {
                int node = base + t;
                if (node < NN) {
                    float m = -1e30f;
#pragma unroll
                    for (int cc = 0; cc < 16; cc++) m = fmaxf(m, sLY[t * 17 + cc]);
                    float s = 0.f;
#pragma unroll
                    for (int cc = 0; cc < 16; cc++) s += expf(sLY[t * 17 + cc] - m);
                    float l = m + logf(s);
#pragma unroll
                    for (int cc = 0; cc < 16; cc++)
                        dout[node * CC + cc] = sLY[t * 17 + cc] - l;
                }
            }
        }
        __syncthreads();
    }
}

// ---------------- launch -----------------------------------------------------
extern "C" void kernel_launch(void* const* d_in, const int* in_sizes, int n_in,
                              void* d_out, int out_size) {
    const float* x       = (const float*)d_in[0];
    const int*   ei      = (const int*)  d_in[1];
    const float* ew      = (const float*)d_in[2];
    const int*   eir     = (const int*)  d_in[3];
    const float* ewr     = (const float*)d_in[4];
    const float* W_first = (const float*)d_in[5];
    const float* b_first = (const float*)d_in[6];
    const float* W_con1  = (const float*)d_in[7];
    const float* b_con1  = (const float*)d_in[8];
    const float* W_con2  = (const float*)d_in[9];
    const float* b_con2  = (const float*)d_in[10];
    const float* W_lin1  = (const float*)d_in[11];
    const float* b_lin1  = (const float*)d_in[12];
    const float* W_out   = (const float*)d_in[13];
    const float* b_out   = (const float*)d_in[14];
    const float* W_ih    = (const float*)d_in[15];
    const float* W_hh    = (const float*)d_in[16];
    const float* b_ih    = (const float*)d_in[17];
    const float* b_hh    = (const float*)d_in[18];
    float* out = (float*)d_out;

    const int SM_F  = F_WORDS * 4;
    const int SM_GH = GH_WORDS * 4;
    const int SM_CG = CG_WORDS * 4;

    static cudaStream_t s1 = nullptr;
    static cudaEvent_t evFork = nullptr, evF = nullptr, evS = nullptr, evG = nullptr;
    if (!s1) {
        cudaStreamCreateWithFlags(&s1, cudaStreamNonBlocking);
        cudaEventCreateWithFlags(&evFork, cudaEventDisableTiming);
        cudaEventCreateWithFlags(&evF, cudaEventDisableTiming);
        cudaEventCreateWithFlags(&evS, cudaEventDisableTiming);
        cudaEventCreateWithFlags(&evG, cudaEventDisableTiming);
        cudaFuncSetAttribute(k_first,
                             cudaFuncAttributeMaxDynamicSharedMemorySize, SM_F);
        cudaFuncSetAttribute(k_ghh,
                             cudaFuncAttributeMaxDynamicSharedMemorySize, SM_GH);
        cudaFuncSetAttribute(k_congru<false>,
                             cudaFuncAttributeMaxDynamicSharedMemorySize, SM_CG);
        cudaFuncSetAttribute(k_congru<true>,
                             cudaFuncAttributeMaxDynamicSharedMemorySize, SM_CG);
    }

    const int PERS = 148;
    const int PROP_BLOCKS = (2 * NN) / 16;   // 12500: 16 dst-nodes per CTA

    // fork: s1 builds the CSR (independent of k_first)
    cudaEventRecord(evFork, 0);
    cudaStreamWaitEvent(s1, evFork, 0);
    k_zcnt<<<(NN + 255) / 256, 256, 0, s1>>>();
    k_hist<<<(EE + 255) / 256, 256, 0, s1>>>(ei, eir);
    k_psum<<<2 * NCH, 1024, 0, s1>>>();
    k_topscan<<<1, 256, 0, s1>>>();
    k_makeoff<<<2 * NCH, 1024, 0, s1>>>();
    k_scatter<<<(EE + 255) / 256, 256, 0, s1>>>(ei, ew, eir, ewr);
    cudaEventRecord(evS, s1);

    // main: k_first, then ghh on s1 (after sort) concurrent with prop1
    k_first<<<PERS, 1024, SM_F>>>(x, W_first, b_first);
    cudaEventRecord(evF, 0);

    cudaStreamWaitEvent(s1, evF, 0);
    k_ghh<<<PERS, 1024, SM_GH, s1>>>(W_hh, b_hh);
    cudaEventRecord(evG, s1);

    // main: prop1 after CSR ready (+ k_first by stream order)
    cudaStreamWaitEvent(0, evS, 0);
    k_prop_csr<<<PROP_BLOCKS, 256>>>(0);

    // congru0 needs ghh
    cudaStreamWaitEvent(0, evG, 0);
    k_congru<false><<<PERS, 1024, SM_CG>>>(W_con1, b_con1, W_ih, b_ih,
                                           W_lin1, b_lin1, nullptr);
    k_prop_csr<<<PROP_BLOCKS, 256>>>(1);
    k_congru<true><<<PERS, 1024, SM_CG>>>(W_con2, b_con2, W_ih, b_ih,
                                          W_out, b_out, out);
}

// round 14
// speedup vs baseline: 1.2950x; 1.0654x over previous
#include <cuda_runtime.h>
#include <cuda_fp16.h>
#include <math.h>
#include <stdint.h>

#define NN 100000
#define FF 128
#define HH 64
#define CC 16
#define EE 1000000
#define NB 782   // ceil(NN/128)
#define NCH 98   // ceil(NN/1024)
#define CHK 1024

// word strides (uint32 units), all ≡ 4 (mod 32) for conflict-free lane maps
#define WP128 68
#define WP64  36
#define WGH  100
#define WH0   36

// ---------------- scratch ----------------------------------------------------
__device__ __align__(16) __half g_h0h[NN * HH];
__device__ __align__(16) __half g_xmidh[NN * HH];
__device__ __align__(16) __half g_ghhh[NN * 192];
__device__ __align__(16) __half g_x1h[NN * HH];
__device__ __align__(16) __half g_x2h[NN * HH];

// CSR build scratch
__device__ int g_cnt1[NN], g_cnt2[NN];
__device__ int g_off1[NN + 1], g_off2[NN + 1];
__device__ int g_pos1[NN], g_pos2[NN];
__device__ int g_psum[2 * NCH];
__device__ __align__(8) int2 g_se1[EE];
__device__ __align__(8) int2 g_se2[EE];

// ---------------- helpers -----------------------------------------------------
__device__ __forceinline__ uint32_t f2h2(float a, float b) {
    __half2 h = __floats2half2_rn(a, b);
    return *(uint32_t*)&h;
}
__device__ __forceinline__ float2 h2f2(uint32_t u) {
    return __half22float2(*(__half2*)&u);
}
__device__ __forceinline__ void mma16(float4& d, uint32_t a0, uint32_t a1,
                                      uint32_t a2, uint32_t a3,
                                      uint32_t b0, uint32_t b1) {
    asm volatile(
        "mma.sync.aligned.m16n8k16.row.col.f32.f16.f16.f32 "
        "{%0,%1,%2,%3},{%4,%5,%6,%7},{%8,%9},{%0,%1,%2,%3};"
        : "+f"(d.x), "+f"(d.y), "+f"(d.z), "+f"(d.w)
        : "r"(a0), "r"(a1), "r"(a2), "r"(a3), "r"(b0), "r"(b1));
}
__device__ __forceinline__ float sigf(float x) {
    return 1.f / (1.f + __expf(-x));
}
__device__ __forceinline__ uint32_t smem_u32(const void* p) {
    uint32_t a;
    asm("{ .reg .u64 t; cvta.to.shared.u64 t, %1; cvt.u32.u64 %0, t; }"
        : "=r"(a) : "l"(p));
    return a;
}
#define CP_ASYNC16(dst, src) \
    asm volatile("cp.async.cg.shared.global [%0], [%1], 16;" \
                 :: "r"(dst), "l"(src) : "memory")
#define CP_COMMIT() asm volatile("cp.async.commit_group;" ::: "memory")
#define CP_WAIT0()  asm volatile("cp.async.wait_group 0;" ::: "memory")

// ================= CSR build ==================================================
__global__ void k_zcnt() {
    int i = blockIdx.x * blockDim.x + threadIdx.x;
    if (i < NN) { g_cnt1[i] = 0; g_cnt2[i] = 0; }
}
__global__ void k_hist(const int* __restrict__ ei1,
                       const int* __restrict__ ei2) {
    int e = blockIdx.x * blockDim.x + threadIdx.x;
    if (e < EE) {
        atomicAdd(&g_cnt1[ei1[EE + e]], 1);
        atomicAdd(&g_cnt2[ei2[EE + e]], 1);
    }
}
__global__ __launch_bounds__(1024) void k_psum() {
    int b = blockIdx.x, t = threadIdx.x;
    const int* cnt = (b < NCH) ? g_cnt1 : g_cnt2;
    int ch = (b < NCH) ? b : b - NCH;
    int n = ch * CHK + t;
    int v = (n < NN) ? cnt[n] : 0;
    __shared__ int ss[1024];
    ss[t] = v; __syncthreads();
    for (int d = 512; d > 0; d >>= 1) {
        if (t < d) ss[t] += ss[t + d];
        __syncthreads();
    }
    if (t == 0) g_psum[b] = ss[0];
}
__global__ __launch_bounds__(256) void k_topscan() {
    __shared__ int s[2 * NCH];
    int t = threadIdx.x;
    if (t < 2 * NCH) s[t] = g_psum[t];
    __syncthreads();
    if (t == 0) { int a = 0; for (int i = 0; i < NCH; i++) { int v = s[i]; s[i] = a; a += v; } }
    if (t == 1) { int a = 0; for (int i = NCH; i < 2 * NCH; i++) { int v = s[i]; s[i] = a; a += v; } }
    __syncthreads();
    if (t < 2 * NCH) g_psum[t] = s[t];
}
__global__ __launch_bounds__(1024) void k_makeoff() {
    int b = blockIdx.x, t = threadIdx.x;
    bool l1 = (b < NCH);
    const int* cnt = l1 ? g_cnt1 : g_cnt2;
    int* off = l1 ? g_off1 : g_off2;
    int* pos = l1 ? g_pos1 : g_pos2;
    int ch = l1 ? b : b - NCH;
    int n = ch * CHK + t;
    int v = (n < NN) ? cnt[n] : 0;
    __shared__ int ss[1024];
    ss[t] = v; __syncthreads();
    for (int d = 1; d < 1024; d <<= 1) {
        int x = (t >= d) ? ss[t - d] : 0;
        __syncthreads();
        ss[t] += x;
        __syncthreads();
    }
    int excl = ss[t] - v + g_psum[b];
    if (n < NN) { off[n] = excl; pos[n] = excl; }
    if (t == 0 && ch == NCH - 1) off[NN] = EE;
}
__global__ void k_scatter(const int* __restrict__ ei1,
                          const float* __restrict__ ew1,
                          const int* __restrict__ ei2,
                          const float* __restrict__ ew2) {
    int e = blockIdx.x * blockDim.x + threadIdx.x;
    if (e < EE) {
        int d1 = ei1[EE + e];
        int p1 = atomicAdd(&g_pos1[d1], 1);
        g_se1[p1] = make_int2(ei1[e], __float_as_int(ew1[e]));
        int d2 = ei2[EE + e];
        int p2 = atomicAdd(&g_pos2[d2], 1);
        g_se2[p2] = make_int2(ei2[e], __float_as_int(ew2[e]));
    }
}

// ---------------- gather-CSR propagation: 16 lanes per dst node --------------
// Accumulate fp32 in registers, store fp16 (single rounding, same as before).
__global__ __launch_bounds__(256) void k_prop_csr(int use_mid) {
    const __half* xin = use_mid ? g_xmidh : g_h0h;
    int gi = blockIdx.x * 16 + (threadIdx.x >> 4);
    int l16 = threadIdx.x & 15;

    const int* off; const int2* se; __half* out; int node;
    if (gi < NN) { node = gi;      off = g_off1; se = g_se1; out = g_x1h; }
    else         { node = gi - NN; off = g_off2; se = g_se2; out = g_x2h; }

    int beg = off[node], end = off[node + 1];
    float4 acc = make_float4(0.f, 0.f, 0.f, 0.f);
    int e = beg;
    for (; e + 1 < end; e += 2) {
        int2 e0 = __ldg(&se[e]);
        int2 e1 = __ldg(&se[e + 1]);
        float w0 = __int_as_float(e0.y), w1 = __int_as_float(e1.y);
        uint2 u0 = *(const uint2*)(xin + e0.x * HH + l16 * 4);
        uint2 u1 = *(const uint2*)(xin + e1.x * HH + l16 * 4);
        float2 a0 = h2f2(u0.x), a1 = h2f2(u0.y);
        float2 b0 = h2f2(u1.x), b1 = h2f2(u1.y);
        acc.x += a0.x * w0 + b0.x * w1;
        acc.y += a0.y * w0 + b0.y * w1;
        acc.z += a1.x * w0 + b1.x * w1;
        acc.w += a1.y * w0 + b1.y * w1;
    }
    if (e < end) {
        int2 e0 = __ldg(&se[e]);
        float w0 = __int_as_float(e0.y);
        uint2 u0 = *(const uint2*)(xin + e0.x * HH + l16 * 4);
        float2 a0 = h2f2(u0.x), a1 = h2f2(u0.y);
        acc.x += a0.x * w0; acc.y += a0.y * w0;
        acc.z += a1.x * w0; acc.w += a1.y * w0;
    }
    uint2 pk;
    pk.x = f2h2(acc.x, acc.y);
    pk.y = f2h2(acc.z, acc.w);
    *(uint2*)(out + node * HH + l16 * 4) = pk;
}

// ---------------- persistent k_first: h0 = x@Wf^T+bf -------------------------
#define F_A    0
#define F_WF   (F_A + 128 * WP128)
#define F_WORDS (F_WF + 64 * WP128)

__global__ __launch_bounds__(1024, 1) void k_first(const float* __restrict__ x,
                                                   const float* __restrict__ Wf,
                                                   const float* __restrict__ bf) {
    extern __shared__ uint32_t sm[];
    uint32_t* sA  = sm + F_A;
    uint32_t* sWf = sm + F_WF;
    __shared__ float sbf[64];
    int t = threadIdx.x;

    for (int i = t; i < 64 * 32; i += 1024) {
        int o = i >> 5, q = i & 31;
        float4 v = *(const float4*)(Wf + o * FF + q * 4);
        sWf[o * WP128 + q * 2]     = f2h2(v.x, v.y);
        sWf[o * WP128 + q * 2 + 1] = f2h2(v.z, v.w);
    }
    if (t < 64) sbf[t] = bf[t];
    __syncthreads();

    int w = t >> 5, lane = t & 31, g = lane >> 2, tig = lane & 3;
    int r0 = (w & 7) * 16, cw = w >> 3;

    for (int tile = blockIdx.x; tile < NB; tile += gridDim.x) {
        int base = tile * 128;
        for (int i = t; i < 128 * 32; i += 1024) {
            int node = i >> 5, q = i & 31;
            float4 v = make_float4(0.f, 0.f, 0.f, 0.f);
            if (base + node < NN)
                v = *(const float4*)(x + (base + node) * FF + q * 4);
            sA[node * WP128 + q * 2]     = f2h2(v.x, v.y);
            sA[node * WP128 + q * 2 + 1] = f2h2(v.z, v.w);
        }
        __syncthreads();

        int cb = cw * 16;
        float4 acc[2] = {};
#pragma unroll
        for (int s = 0; s < 8; s++) {
            int ko = s * 8;
            uint32_t a0 = sA[(r0 + g) * WP128 + ko + tig];
            uint32_t a1 = sA[(r0 + g + 8) * WP128 + ko + tig];
            uint32_t a2 = sA[(r0 + g) * WP128 + ko + tig + 4];
            uint32_t a3 = sA[(r0 + g + 8) * WP128 + ko + tig + 4];
#pragma unroll
            for (int nt = 0; nt < 2; nt++) {
                int o = cb + nt * 8 + g;
                mma16(acc[nt], a0, a1, a2, a3,
                      sWf[o * WP128 + ko + tig], sWf[o * WP128 + ko + tig + 4]);
            }
        }
#pragma unroll
        for (int nt = 0; nt < 2; nt++) {
            int c = cb + nt * 8 + tig * 2;
            int n1 = base + r0 + g, n2 = n1 + 8;
            if (n1 < NN)
                *(uint32_t*)(g_h0h + n1 * HH + c) =
                    f2h2(acc[nt].x + sbf[c], acc[nt].y + sbf[c + 1]);
            if (n2 < NN)
                *(uint32_t*)(g_h0h + n2 * HH + c) =
                    f2h2(acc[nt].z + sbf[c], acc[nt].w + sbf[c + 1]);
        }
        __syncthreads();
    }
}

// ---------------- persistent k_ghh: ghh = h0 @ Whh^T + bhh -------------------
#define GH_W   0
#define GH_H   (GH_W + 192 * WP64)
#define GH_WORDS (GH_H + 128 * WP64)

__global__ __launch_bounds__(1024, 1) void k_ghh(const float* __restrict__ Whh,
                                                 const float* __restrict__ bhh) {
    extern __shared__ uint32_t sm[];
    uint32_t* sW = sm + GH_W;
    uint32_t* sH = sm + GH_H;
    __shared__ float sbhh[192];
    int t = threadIdx.x;
    uint32_t sH_b = smem_u32(sH);

    for (int i = t; i < 192 * 16; i += 1024) {
        int o = i >> 4, q = i & 15;
        float4 v = *(const float4*)(Whh + o * HH + q * 4);
        sW[o * WP64 + q * 2]     = f2h2(v.x, v.y);
        sW[o * WP64 + q * 2 + 1] = f2h2(v.z, v.w);
    }
    if (t < 192) sbhh[t] = bhh[t];
    __syncthreads();

    int w = t >> 5, lane = t & 31, g = lane >> 2, tig = lane & 3;
    int r0 = (w & 7) * 16, cw = w >> 3;

    for (int tile = blockIdx.x; tile < NB; tile += gridDim.x) {
        int base = tile * 128;
        for (int i = t; i < 128 * 8; i += 1024) {
            int row = i >> 3, ch = i & 7;
            int n = base + row;
            if (n < NN)
                CP_ASYNC16(sH_b + (row * WP64 + ch * 4) * 4,
                           (const char*)(g_h0h + n * HH) + ch * 16);
        }
        CP_COMMIT();
        CP_WAIT0();
        __syncthreads();

        int cb = cw * 48;
        float4 acc[6] = {};
#pragma unroll
        for (int s = 0; s < 4; s++) {
            int ko = s * 8;
            uint32_t a0 = sH[(r0 + g) * WP64 + ko + tig];
            uint32_t a1 = sH[(r0 + g + 8) * WP64 + ko + tig];
            uint32_t a2 = sH[(r0 + g) * WP64 + ko + tig + 4];
            uint32_t a3 = sH[(r0 + g + 8) * WP64 + ko + tig + 4];
#pragma unroll
            for (int nt = 0; nt < 6; nt++) {
                int o = cb + nt * 8 + g;
                mma16(acc[nt], a0, a1, a2, a3,
                      sW[o * WP64 + ko + tig], sW[o * WP64 + ko + tig + 4]);
            }
        }
#pragma unroll
        for (int nt = 0; nt < 6; nt++) {
            int c = cb + nt * 8 + tig * 2;
            int n1 = base + r0 + g, n2 = n1 + 8;
            if (n1 < NN)
                *(uint32_t*)(g_ghhh + n1 * 192 + c) =
                    f2h2(acc[nt].x + sbhh[c], acc[nt].y + sbhh[c + 1]);
            if (n2 < NN)
                *(uint32_t*)(g_ghhh + n2 * 192 + c) =
                    f2h2(acc[nt].z + sbhh[c], acc[nt].w + sbhh[c + 1]);
        }
        __syncthreads();
    }
}

// ---------------- persistent fused concat-linear + GRU + out ----------------
#define O_A    0
#define O_WC   (O_A + 128 * WP128)
#define O_WIH  (O_WC + 64 * WP128)
#define O_WL   (O_WIH + 192 * WP64)
#define O_G    (O_WL + 64 * WP64)
#define O_GH   (O_G + 128 * WP64)
#define O_H0   (O_GH + 128 * WGH)
#define O_BC   (O_H0 + 128 * WH0)
#define O_BIH  (O_BC + 64)
#define O_BL   (O_BIH + 192)
#define O_LY   (O_BL + 64)
#define CG_WORDS (O_LY + 128 * 17)

template <bool FINAL>
__global__ __launch_bounds__(1024, 1) void k_congru(
    const float* __restrict__ Wc,  const float* __restrict__ bc,
    const float* __restrict__ Wih, const float* __restrict__ bih,
    const float* __restrict__ Wl,  const float* __restrict__ bl,
    float* __restrict__ dout) {
    extern __shared__ uint32_t sm[];
    uint32_t* sA   = sm + O_A;
    uint32_t* sWc  = sm + O_WC;
    uint32_t* sWih = sm + O_WIH;
    uint32_t* sWl  = sm + O_WL;
    uint32_t* sG   = sm + O_G;
    uint32_t* sGH  = sm + O_GH;
    uint32_t* sH0  = sm + O_H0;
    float* sbc  = (float*)(sm + O_BC);
    float* sbih = (float*)(sm + O_BIH);
    float* sbl  = (float*)(sm + O_BL);
    float* sLY  = (float*)(sm + O_LY);
    const int OC = FINAL ? CC : HH;

    int t = threadIdx.x;
    uint32_t sGH_b = smem_u32(sGH);
    uint32_t sH0_b = smem_u32(sH0);

    for (int i = t; i < 64 * 32; i += 1024) {
        int o = i >> 5, q = i & 31;
        float4 v = *(const float4*)(Wc + o * FF + q * 4);
        sWc[o * WP128 + q * 2]     = f2h2(v.x, v.y);
        sWc[o * WP128 + q * 2 + 1] = f2h2(v.z, v.w);
    }
    for (int i = t; i < 192 * 16; i += 1024) {
        int o = i >> 4, q = i & 15;
        float4 v = *(const float4*)(Wih + o * HH + q * 4);
        sWih[o * WP64 + q * 2]     = f2h2(v.x, v.y);
        sWih[o * WP64 + q * 2 + 1] = f2h2(v.z, v.w);
    }
    for (int i = t; i < OC * 16; i += 1024) {
        int o = i >> 4, q = i & 15;
        float4 v = *(const float4*)(Wl + o * HH + q * 4);
        sWl[o * WP64 + q * 2]     = f2h2(v.x, v.y);
        sWl[o * WP64 + q * 2 + 1] = f2h2(v.z, v.w);
    }
    if (t < 64)  sbc[t]  = bc[t];
    if (t < 192) sbih[t] = bih[t];
    if (t < OC)  sbl[t]  = bl[t];
    __syncthreads();

    int w = t >> 5, lane = t & 31, g = lane >> 2, tig = lane & 3;
    int r0 = (w & 7) * 16, cw = w >> 3, cb = cw * 16;

    for (int tile = blockIdx.x; tile < NB; tile += gridDim.x) {
        int base = tile * 128;
        // stage concat input: straight uint4 copy of pre-packed fp16
        for (int i = t; i < 128 * 8; i += 1024) {
            int node = i >> 3, q = i & 7;   // 8 chunks of 4 words (8 halves)
            int n = base + node;
            uint4 v1 = make_uint4(0u, 0u, 0u, 0u), v2 = v1;
            if (n < NN) {
                v1 = *(const uint4*)(g_x1h + n * HH + q * 8);
                v2 = *(const uint4*)(g_x2h + n * HH + q * 8);
            }
            *(uint4*)(sA + node * WP128 + q * 4)      = v1;
            *(uint4*)(sA + node * WP128 + 32 + q * 4) = v2;
        }
        for (int i = t; i < 128 * 24; i += 1024) {
            int row = i / 24, ch = i % 24;
            int n = base + row;
            if (n < NN)
                CP_ASYNC16(sGH_b + (row * WGH + ch * 4) * 4,
                           (const char*)(g_ghhh + n * 192) + ch * 16);
        }
        for (int i = t; i < 128 * 8; i += 1024) {
            int row = i >> 3, ch = i & 7;
            int n = base + row;
            if (n < NN)
                CP_ASYNC16(sH0_b + (row * WH0 + ch * 4) * 4,
                           (const char*)(g_h0h + n * HH) + ch * 16);
        }
        CP_COMMIT();
        __syncthreads();

        // phase 1
        {
            float4 acc[2] = {};
#pragma unroll
            for (int s = 0; s < 8; s++) {
                int ko = s * 8;
                uint32_t a0 = sA[(r0 + g) * WP128 + ko + tig];
                uint32_t a1 = sA[(r0 + g + 8) * WP128 + ko + tig];
                uint32_t a2 = sA[(r0 + g) * WP128 + ko + tig + 4];
                uint32_t a3 = sA[(r0 + g + 8) * WP128 + ko + tig + 4];
#pragma unroll
                for (int nt = 0; nt < 2; nt++) {
                    int o = cb + nt * 8 + g;
                    mma16(acc[nt], a0, a1, a2, a3,
                          sWc[o * WP128 + ko + tig], sWc[o * WP128 + ko + tig + 4]);
                }
            }
#pragma unroll
            for (int nt = 0; nt < 2; nt++) {
                int c = cb + nt * 8 + tig * 2;
                int cwd = c >> 1;
                sG[(r0 + g) * WP64 + cwd] =
                    f2h2(acc[nt].x + sbc[c], acc[nt].y + sbc[c + 1]);
                sG[(r0 + g + 8) * WP64 + cwd] =
                    f2h2(acc[nt].z + sbc[c], acc[nt].w + sbc[c + 1]);
            }
        }
        __syncthreads();

        // phase 2
        float4 d2[3][2];
#pragma unroll
        for (int gt = 0; gt < 3; gt++)
#pragma unroll
            for (int nt = 0; nt < 2; nt++)
                d2[gt][nt] = make_float4(0.f, 0.f, 0.f, 0.f);
#pragma unroll
        for (int s = 0; s < 4; s++) {
            int ko = s * 8;
            uint32_t a0 = sG[(r0 + g) * WP64 + ko + tig];
            uint32_t a1 = sG[(r0 + g + 8) * WP64 + ko + tig];
            uint32_t a2 = sG[(r0 + g) * WP64 + ko + tig + 4];
            uint32_t a3 = sG[(r0 + g + 8) * WP64 + ko + tig + 4];
#pragma unroll
            for (int gt = 0; gt < 3; gt++)
#pragma unroll
                for (int nt = 0; nt < 2; nt++) {
                    int o = gt * 64 + cb + nt * 8 + g;
                    mma16(d2[gt][nt], a0, a1, a2, a3,
                          sWih[o * WP64 + ko + tig], sWih[o * WP64 + ko + tig + 4]);
                }
        }

        CP_WAIT0();
        __syncthreads();

        // phase 3: GRU
        float hn[2][4];
#pragma unroll
        for (int nt = 0; nt < 2; nt++) {
            int c = cb + nt * 8 + tig * 2;
            int cwd = c >> 1;
#pragma unroll
            for (int half = 0; half < 2; half++) {
                int nl = r0 + g + half * 8;
                float vr0 = half ? d2[0][nt].z : d2[0][nt].x;
                float vr1 = half ? d2[0][nt].w : d2[0][nt].y;
                float vz0 = half ? d2[1][nt].z : d2[1][nt].x;
                float vz1 = half ? d2[1][nt].w : d2[1][nt].y;
                float vn0 = half ? d2[2][nt].z : d2[2][nt].x;
                float vn1 = half ? d2[2][nt].w : d2[2][nt].y;
                float2 gr = h2f2(sGH[nl * WGH + cwd]);
                float2 gz = h2f2(sGH[nl * WGH + 32 + cwd]);
                float2 gn = h2f2(sGH[nl * WGH + 64 + cwd]);
                float2 h  = h2f2(sH0[nl * WH0 + cwd]);
                float r = sigf(vr0 + sbih[c] + gr.x);
                float z = sigf(vz0 + sbih[64 + c] + gz.x);
                float n = tanhf(vn0 + sbih[128 + c] + r * gn.x);
                hn[nt][half * 2] = (1.f - z) * n + z * h.x;
                r = sigf(vr1 + sbih[c + 1] + gr.y);
                z = sigf(vz1 + sbih[64 + c + 1] + gz.y);
                n = tanhf(vn1 + sbih[128 + c + 1] + r * gn.y);
                hn[nt][half * 2 + 1] = (1.f - z) * n + z * h.y;
            }
        }
        __syncthreads();
#pragma unroll
        for (int nt = 0; nt < 2; nt++) {
            int c = cb + nt * 8 + tig * 2;
            int cwd = c >> 1;
            sG[(r0 + g) * WP64 + cwd]     = f2h2(hn[nt][0], hn[nt][1]);
            sG[(r0 + g + 8) * WP64 + cwd] = f2h2(hn[nt][2], hn[nt][3]);
        }
        __syncthreads();

        // phase 4
        if (!FINAL) {
            float4 acc[2] = {};
#pragma unroll
            for (int s = 0; s < 4; s++) {
                int ko = s * 8;
                uint32_t a0 = sG[(r0 + g) * WP64 + ko + tig];
                uint32_t a1 = sG[(r0 + g + 8) * WP64 + ko + tig];
                uint32_t a2 = sG[(r0 + g) * WP64 + ko + tig + 4];
                uint32_t a3 = sG[(r0 + g + 8) * WP64 + ko + tig + 4];
#pragma unroll
                for (int nt = 0; nt < 2; nt++) {
                    int o = cb + nt * 8 + g;
                    mma16(acc[nt], a0, a1, a2, a3,
                          sWl[o * WP64 + ko + tig], sWl[o * WP64 + ko + tig + 4]);
                }
            }
#pragma unroll
            for (int nt = 0; nt < 2; nt++) {
                int c = cb + nt * 8 + tig * 2;
                int n1 = base + r0 + g, n2 = n1 + 8;
                if (n1 < NN)
                    *(uint32_t*)(g_xmidh + n1 * HH + c) =
                        f2h2(acc[nt].x + sbl[c], acc[nt].y + sbl[c + 1]);
                if (n2 < NN)
                    *(uint32_t*)(g_xmidh + n2 * HH + c) =
                        f2h2(acc[nt].z + sbl[c], acc[nt].w + sbl[c + 1]);
            }
        } else {
            if (cw < 2) {
                float4 acc = make_float4(0.f, 0.f, 0.f, 0.f);
                int c0f = cw * 8;
#pragma unroll
                for (int s = 0; s < 4; s++) {
                    int ko = s * 8;
                    uint32_t a0 = sG[(r0 + g) * WP64 + ko + tig];
                    uint32_t a1 = sG[(r0 + g + 8) * WP64 + ko + tig];
                    uint32_t a2 = sG[(r0 + g) * WP64 + ko + tig + 4];
                    uint32_t a3 = sG[(r0 + g + 8) * WP64 + ko + tig + 4];
                    int o = c0f + g;
                    mma16(acc, a0, a1, a2, a3,
                          sWl[o * WP64 + ko + tig], sWl[o * WP64 + ko + tig + 4]);
                }
                int c = c0f + tig * 2;
                sLY[(r0 + g) * 17 + c]         = acc.x + sbl[c];
                sLY[(r0 + g) * 17 + c + 1]     = acc.y + sbl[c + 1];
                sLY[(r0 + g + 8) * 17 + c]     = acc.z + sbl[c];
                sLY[(r0 + g + 8) * 17 + c + 1] = acc.w + sbl[c + 1];
            }
            __syncthreads();
            if (t < 128) {
                int node = base + t;
                if (node < NN) {
                    float m = -1e30f;
#pragma unroll
                    for (int cc = 0; cc < 16; cc++) m = fmaxf(m, sLY[t * 17 + cc]);
                    float s = 0.f;
#pragma unroll
                    for (int cc = 0; cc < 16; cc++) s += expf(sLY[t * 17 + cc] - m);
                    float l = m + logf(s);
#pragma unroll
                    for (int cc = 0; cc < 16; cc++)
                        dout[node * CC + cc] = sLY[t * 17 + cc] - l;
                }
            }
        }
        __syncthreads();
    }
}

// ---------------- launch -----------------------------------------------------
extern "C" void kernel_launch(void* const* d_in, const int* in_sizes, int n_in,
                              void* d_out, int out_size) {
    const float* x       = (const float*)d_in[0];
    const int*   ei      = (const int*)  d_in[1];
    const float* ew      = (const float*)d_in[2];
    const int*   eir     = (const int*)  d_in[3];
    const float* ewr     = (const float*)d_in[4];
    const float* W_first = (const float*)d_in[5];
    const float* b_first = (const float*)d_in[6];
    const float* W_con1  = (const float*)d_in[7];
    const float* b_con1  = (const float*)d_in[8];
    const float* W_con2  = (const float*)d_in[9];
    const float* b_con2  = (const float*)d_in[10];
    const float* W_lin1  = (const float*)d_in[11];
    const float* b_lin1  = (const float*)d_in[12];
    const float* W_out   = (const float*)d_in[13];
    const float* b_out   = (const float*)d_in[14];
    const float* W_ih    = (const float*)d_in[15];
    const float* W_hh    = (const float*)d_in[16];
    const float* b_ih    = (const float*)d_in[17];
    const float* b_hh    = (const float*)d_in[18];
    float* out = (float*)d_out;

    const int SM_F  = F_WORDS * 4;
    const int SM_GH = GH_WORDS * 4;
    const int SM_CG = CG_WORDS * 4;

    static cudaStream_t s1 = nullptr;
    static cudaEvent_t evFork = nullptr, evF = nullptr, evS = nullptr, evG = nullptr;
    if (!s1) {
        cudaStreamCreateWithFlags(&s1, cudaStreamNonBlocking);
        cudaEventCreateWithFlags(&evFork, cudaEventDisableTiming);
        cudaEventCreateWithFlags(&evF, cudaEventDisableTiming);
        cudaEventCreateWithFlags(&evS, cudaEventDisableTiming);
        cudaEventCreateWithFlags(&evG, cudaEventDisableTiming);
        cudaFuncSetAttribute(k_first,
                             cudaFuncAttributeMaxDynamicSharedMemorySize, SM_F);
        cudaFuncSetAttribute(k_ghh,
                             cudaFuncAttributeMaxDynamicSharedMemorySize, SM_GH);
        cudaFuncSetAttribute(k_congru<false>,
                             cudaFuncAttributeMaxDynamicSharedMemorySize, SM_CG);
        cudaFuncSetAttribute(k_congru<true>,
                             cudaFuncAttributeMaxDynamicSharedMemorySize, SM_CG);
    }

    const int PERS = 148;
    const int PROP_BLOCKS = (2 * NN) / 16;   // 12500: 16 dst-nodes per CTA

    // fork: s1 builds the CSR (independent of k_first)
    cudaEventRecord(evFork, 0);
    cudaStreamWaitEvent(s1, evFork, 0);
    k_zcnt<<<(NN + 255) / 256, 256, 0, s1>>>();
    k_hist<<<(EE + 255) / 256, 256, 0, s1>>>(ei, eir);
    k_psum<<<2 * NCH, 1024, 0, s1>>>();
    k_topscan<<<1, 256, 0, s1>>>();
    k_makeoff<<<2 * NCH, 1024, 0, s1>>>();
    k_scatter<<<(EE + 255) / 256, 256, 0, s1>>>(ei, ew, eir, ewr);
    cudaEventRecord(evS, s1);

    // main: k_first, then ghh on s1 (after sort) concurrent with prop1
    k_first<<<PERS, 1024, SM_F>>>(x, W_first, b_first);
    cudaEventRecord(evF, 0);

    cudaStreamWaitEvent(s1, evF, 0);
    k_ghh<<<PERS, 1024, SM_GH, s1>>>(W_hh, b_hh);
    cudaEventRecord(evG, s1);

    // main: prop1 after CSR ready (+ k_first by stream order)
    cudaStreamWaitEvent(0, evS, 0);
    k_prop_csr<<<PROP_BLOCKS, 256>>>(0);

    // congru0 needs ghh
    cudaStreamWaitEvent(0, evG, 0);
    k_congru<false><<<PERS, 1024, SM_CG>>>(W_con1, b_con1, W_ih, b_ih,
                                           W_lin1, b_lin1, nullptr);
    k_prop_csr<<<PROP_BLOCKS, 256>>>(1);
    k_congru<true><<<PERS, 1024, SM_CG>>>(W_con2, b_con2, W_ih, b_ih,
                                          W_out, b_out, out);
}

// round 15
// speedup vs baseline: 1.3777x; 1.0639x over previous
#include <cuda_runtime.h>
#include <cuda_fp16.h>
#include <math.h>
#include <stdint.h>

#define NN 100000
#define FF 128
#define HH 64
#define CC 16
#define EE 1000000
#define NB 782   // ceil(NN/128)
#define NCH 98   // ceil(NN/1024)
#define CHK 1024

// word strides (uint32 units)
#define WP128 68
#define WP64  36
#define WGH  100
#define WH0   36

// ---------------- scratch ----------------------------------------------------
__device__ __align__(16) __half g_h0h[NN * HH];
__device__ __align__(16) __half g_xmidh[NN * HH];
__device__ __align__(16) __half g_x1h[NN * HH];
__device__ __align__(16) __half g_x2h[NN * HH];

// CSR build scratch
__device__ int g_cnt1[NN], g_cnt2[NN];
__device__ int g_off1[NN + 1], g_off2[NN + 1];
__device__ int g_pos1[NN], g_pos2[NN];
__device__ int g_psum[2 * NCH];
__device__ __align__(8) int2 g_se1[EE];
__device__ __align__(8) int2 g_se2[EE];

// ---------------- helpers -----------------------------------------------------
__device__ __forceinline__ uint32_t f2h2(float a, float b) {
    __half2 h = __floats2half2_rn(a, b);
    return *(uint32_t*)&h;
}
__device__ __forceinline__ float2 h2f2(uint32_t u) {
    return __half22float2(*(__half2*)&u);
}
__device__ __forceinline__ void mma16(float4& d, uint32_t a0, uint32_t a1,
                                      uint32_t a2, uint32_t a3,
                                      uint32_t b0, uint32_t b1) {
    asm volatile(
        "mma.sync.aligned.m16n8k16.row.col.f32.f16.f16.f32 "
        "{%0,%1,%2,%3},{%4,%5,%6,%7},{%8,%9},{%0,%1,%2,%3};"
        : "+f"(d.x), "+f"(d.y), "+f"(d.z), "+f"(d.w)
        : "r"(a0), "r"(a1), "r"(a2), "r"(a3), "r"(b0), "r"(b1));
}
__device__ __forceinline__ float sigf(float x) {
    return 1.f / (1.f + __expf(-x));
}
__device__ __forceinline__ uint32_t smem_u32(const void* p) {
    uint32_t a;
    asm("{ .reg .u64 t; cvta.to.shared.u64 t, %1; cvt.u32.u64 %0, t; }"
        : "=r"(a) : "l"(p));
    return a;
}
#define CP_ASYNC16(dst, src) \
    asm volatile("cp.async.cg.shared.global [%0], [%1], 16;" \
                 :: "r"(dst), "l"(src) : "memory")
#define CP_COMMIT() asm volatile("cp.async.commit_group;" ::: "memory")
#define CP_WAIT0()  asm volatile("cp.async.wait_group 0;" ::: "memory")

// ================= CSR build ==================================================
__global__ void k_zcnt() {
    int i = blockIdx.x * blockDim.x + threadIdx.x;
    if (i < NN) { g_cnt1[i] = 0; g_cnt2[i] = 0; }
}
__global__ void k_hist(const int* __restrict__ ei1,
                       const int* __restrict__ ei2) {
    int e = blockIdx.x * blockDim.x + threadIdx.x;
    if (e < EE) {
        atomicAdd(&g_cnt1[ei1[EE + e]], 1);
        atomicAdd(&g_cnt2[ei2[EE + e]], 1);
    }
}
__global__ __launch_bounds__(1024) void k_psum() {
    int b = blockIdx.x, t = threadIdx.x;
    const int* cnt = (b < NCH) ? g_cnt1 : g_cnt2;
    int ch = (b < NCH) ? b : b - NCH;
    int n = ch * CHK + t;
    int v = (n < NN) ? cnt[n] : 0;
    __shared__ int ss[1024];
    ss[t] = v; __syncthreads();
    for (int d = 512; d > 0; d >>= 1) {
        if (t < d) ss[t] += ss[t + d];
        __syncthreads();
    }
    if (t == 0) g_psum[b] = ss[0];
}
__global__ __launch_bounds__(256) void k_topscan() {
    __shared__ int s[2 * NCH];
    int t = threadIdx.x;
    if (t < 2 * NCH) s[t] = g_psum[t];
    __syncthreads();
    if (t == 0) { int a = 0; for (int i = 0; i < NCH; i++) { int v = s[i]; s[i] = a; a += v; } }
    if (t == 1) { int a = 0; for (int i = NCH; i < 2 * NCH; i++) { int v = s[i]; s[i] = a; a += v; } }
    __syncthreads();
    if (t < 2 * NCH) g_psum[t] = s[t];
}
__global__ __launch_bounds__(1024) void k_makeoff() {
    int b = blockIdx.x, t = threadIdx.x;
    bool l1 = (b < NCH);
    const int* cnt = l1 ? g_cnt1 : g_cnt2;
    int* off = l1 ? g_off1 : g_off2;
    int* pos = l1 ? g_pos1 : g_pos2;
    int ch = l1 ? b : b - NCH;
    int n = ch * CHK + t;
    int v = (n < NN) ? cnt[n] : 0;
    __shared__ int ss[1024];
    ss[t] = v; __syncthreads();
    for (int d = 1; d < 1024; d <<= 1) {
        int x = (t >= d) ? ss[t - d] : 0;
        __syncthreads();
        ss[t] += x;
        __syncthreads();
    }
    int excl = ss[t] - v + g_psum[b];
    if (n < NN) { off[n] = excl; pos[n] = excl; }
    if (t == 0 && ch == NCH - 1) off[NN] = EE;
}
__global__ void k_scatter(const int* __restrict__ ei1,
                          const float* __restrict__ ew1,
                          const int* __restrict__ ei2,
                          const float* __restrict__ ew2) {
    int e = blockIdx.x * blockDim.x + threadIdx.x;
    if (e < EE) {
        int d1 = ei1[EE + e];
        int p1 = atomicAdd(&g_pos1[d1], 1);
        g_se1[p1] = make_int2(ei1[e], __float_as_int(ew1[e]));
        int d2 = ei2[EE + e];
        int p2 = atomicAdd(&g_pos2[d2], 1);
        g_se2[p2] = make_int2(ei2[e], __float_as_int(ew2[e]));
    }
}

// ---------------- gather-CSR propagation: 16 lanes per dst node --------------
__global__ __launch_bounds__(256) void k_prop_csr(int use_mid) {
    const __half* xin = use_mid ? g_xmidh : g_h0h;
    int gi = blockIdx.x * 16 + (threadIdx.x >> 4);
    int l16 = threadIdx.x & 15;

    const int* off; const int2* se; __half* out; int node;
    if (gi < NN) { node = gi;      off = g_off1; se = g_se1; out = g_x1h; }
    else         { node = gi - NN; off = g_off2; se = g_se2; out = g_x2h; }

    int beg = off[node], end = off[node + 1];
    float4 acc = make_float4(0.f, 0.f, 0.f, 0.f);
    int e = beg;
    for (; e + 3 < end; e += 4) {
        int2 e0 = __ldg(&se[e]);
        int2 e1 = __ldg(&se[e + 1]);
        int2 e2 = __ldg(&se[e + 2]);
        int2 e3 = __ldg(&se[e + 3]);
        uint2 u0 = *(const uint2*)(xin + e0.x * HH + l16 * 4);
        uint2 u1 = *(const uint2*)(xin + e1.x * HH + l16 * 4);
        uint2 u2 = *(const uint2*)(xin + e2.x * HH + l16 * 4);
        uint2 u3 = *(const uint2*)(xin + e3.x * HH + l16 * 4);
        float w0 = __int_as_float(e0.y), w1 = __int_as_float(e1.y);
        float w2 = __int_as_float(e2.y), w3 = __int_as_float(e3.y);
        float2 a0 = h2f2(u0.x), a1 = h2f2(u0.y);
        float2 b0 = h2f2(u1.x), b1 = h2f2(u1.y);
        float2 c0 = h2f2(u2.x), c1 = h2f2(u2.y);
        float2 d0 = h2f2(u3.x), d1 = h2f2(u3.y);
        acc.x += a0.x * w0 + b0.x * w1 + c0.x * w2 + d0.x * w3;
        acc.y += a0.y * w0 + b0.y * w1 + c0.y * w2 + d0.y * w3;
        acc.z += a1.x * w0 + b1.x * w1 + c1.x * w2 + d1.x * w3;
        acc.w += a1.y * w0 + b1.y * w1 + c1.y * w2 + d1.y * w3;
    }
    for (; e < end; e++) {
        int2 e0 = __ldg(&se[e]);
        float w0 = __int_as_float(e0.y);
        uint2 u0 = *(const uint2*)(xin + e0.x * HH + l16 * 4);
        float2 a0 = h2f2(u0.x), a1 = h2f2(u0.y);
        acc.x += a0.x * w0; acc.y += a0.y * w0;
        acc.z += a1.x * w0; acc.w += a1.y * w0;
    }
    uint2 pk;
    pk.x = f2h2(acc.x, acc.y);
    pk.y = f2h2(acc.z, acc.w);
    *(uint2*)(out + node * HH + l16 * 4) = pk;
}

// ---------------- persistent k_first: h0 = x@Wf^T+bf -------------------------
#define F_A    0
#define F_WF   (F_A + 128 * WP128)
#define F_WORDS (F_WF + 64 * WP128)

__global__ __launch_bounds__(1024, 1) void k_first(const float* __restrict__ x,
                                                   const float* __restrict__ Wf,
                                                   const float* __restrict__ bf) {
    extern __shared__ uint32_t sm[];
    uint32_t* sA  = sm + F_A;
    uint32_t* sWf = sm + F_WF;
    __shared__ float sbf[64];
    int t = threadIdx.x;

    for (int i = t; i < 64 * 32; i += 1024) {
        int o = i >> 5, q = i & 31;
        float4 v = *(const float4*)(Wf + o * FF + q * 4);
        sWf[o * WP128 + q * 2]     = f2h2(v.x, v.y);
        sWf[o * WP128 + q * 2 + 1] = f2h2(v.z, v.w);
    }
    if (t < 64) sbf[t] = bf[t];
    __syncthreads();

    int w = t >> 5, lane = t & 31, g = lane >> 2, tig = lane & 3;
    int r0 = (w & 7) * 16, cw = w >> 3;

    for (int tile = blockIdx.x; tile < NB; tile += gridDim.x) {
        int base = tile * 128;
        for (int i = t; i < 128 * 32; i += 1024) {
            int node = i >> 5, q = i & 31;
            float4 v = make_float4(0.f, 0.f, 0.f, 0.f);
            if (base + node < NN)
                v = *(const float4*)(x + (base + node) * FF + q * 4);
            sA[node * WP128 + q * 2]     = f2h2(v.x, v.y);
            sA[node * WP128 + q * 2 + 1] = f2h2(v.z, v.w);
        }
        __syncthreads();

        int cb = cw * 16;
        float4 acc[2] = {};
#pragma unroll
        for (int s = 0; s < 8; s++) {
            int ko = s * 8;
            uint32_t a0 = sA[(r0 + g) * WP128 + ko + tig];
            uint32_t a1 = sA[(r0 + g + 8) * WP128 + ko + tig];
            uint32_t a2 = sA[(r0 + g) * WP128 + ko + tig + 4];
            uint32_t a3 = sA[(r0 + g + 8) * WP128 + ko + tig + 4];
#pragma unroll
            for (int nt = 0; nt < 2; nt++) {
                int o = cb + nt * 8 + g;
                mma16(acc[nt], a0, a1, a2, a3,
                      sWf[o * WP128 + ko + tig], sWf[o * WP128 + ko + tig + 4]);
            }
        }
#pragma unroll
        for (int nt = 0; nt < 2; nt++) {
            int c = cb + nt * 8 + tig * 2;
            int n1 = base + r0 + g, n2 = n1 + 8;
            if (n1 < NN)
                *(uint32_t*)(g_h0h + n1 * HH + c) =
                    f2h2(acc[nt].x + sbf[c], acc[nt].y + sbf[c + 1]);
            if (n2 < NN)
                *(uint32_t*)(g_h0h + n2 * HH + c) =
                    f2h2(acc[nt].z + sbf[c], acc[nt].w + sbf[c + 1]);
        }
        __syncthreads();
    }
}

// ---------------- persistent fused: ghh-in-kernel + concat + GRU + out -------
#define O_A    0
#define O_WC   (O_A + 128 * WP128)
#define O_WIH  (O_WC + 64 * WP128)
#define O_WHH  (O_WIH + 192 * WP64)
#define O_WL   (O_WHH + 192 * WP64)
#define O_G    (O_WL + 64 * WP64)
#define O_GH   (O_G + 128 * WP64)
#define O_H0   (O_GH + 128 * WGH)
#define O_BC   (O_H0 + 128 * WH0)
#define O_BIH  (O_BC + 64)
#define O_BHH  (O_BIH + 192)
#define O_BL   (O_BHH + 192)
#define O_LY   (O_BL + 64)
#define CG_WORDS (O_LY + 128 * 17)

template <bool FINAL>
__global__ __launch_bounds__(1024, 1) void k_congru(
    const float* __restrict__ Wc,  const float* __restrict__ bc,
    const float* __restrict__ Wih, const float* __restrict__ bih,
    const float* __restrict__ Whh, const float* __restrict__ bhh,
    const float* __restrict__ Wl,  const float* __restrict__ bl,
    float* __restrict__ dout) {
    extern __shared__ uint32_t sm[];
    uint32_t* sA   = sm + O_A;
    uint32_t* sWc  = sm + O_WC;
    uint32_t* sWih = sm + O_WIH;
    uint32_t* sWhh = sm + O_WHH;
    uint32_t* sWl  = sm + O_WL;
    uint32_t* sG   = sm + O_G;
    uint32_t* sGH  = sm + O_GH;
    uint32_t* sH0  = sm + O_H0;
    float* sbc  = (float*)(sm + O_BC);
    float* sbih = (float*)(sm + O_BIH);
    float* sbhh = (float*)(sm + O_BHH);
    float* sbl  = (float*)(sm + O_BL);
    float* sLY  = (float*)(sm + O_LY);
    const int OC = FINAL ? CC : HH;

    int t = threadIdx.x;
    uint32_t sH0_b = smem_u32(sH0);

    for (int i = t; i < 64 * 32; i += 1024) {
        int o = i >> 5, q = i & 31;
        float4 v = *(const float4*)(Wc + o * FF + q * 4);
        sWc[o * WP128 + q * 2]     = f2h2(v.x, v.y);
        sWc[o * WP128 + q * 2 + 1] = f2h2(v.z, v.w);
    }
    for (int i = t; i < 192 * 16; i += 1024) {
        int o = i >> 4, q = i & 15;
        float4 v = *(const float4*)(Wih + o * HH + q * 4);
        sWih[o * WP64 + q * 2]     = f2h2(v.x, v.y);
        sWih[o * WP64 + q * 2 + 1] = f2h2(v.z, v.w);
        float4 u = *(const float4*)(Whh + o * HH + q * 4);
        sWhh[o * WP64 + q * 2]     = f2h2(u.x, u.y);
        sWhh[o * WP64 + q * 2 + 1] = f2h2(u.z, u.w);
    }
    for (int i = t; i < OC * 16; i += 1024) {
        int o = i >> 4, q = i & 15;
        float4 v = *(const float4*)(Wl + o * HH + q * 4);
        sWl[o * WP64 + q * 2]     = f2h2(v.x, v.y);
        sWl[o * WP64 + q * 2 + 1] = f2h2(v.z, v.w);
    }
    if (t < 64)  sbc[t]  = bc[t];
    if (t < 192) sbih[t] = bih[t];
    if (t >= 256 && t < 448) sbhh[t - 256] = bhh[t - 256];
    if (t >= 512 && t < 512 + OC) sbl[t - 512] = bl[t - 512];
    __syncthreads();

    int w = t >> 5, lane = t & 31, g = lane >> 2, tig = lane & 3;
    int r0 = (w & 7) * 16, cw = w >> 3, cb = cw * 16;

    for (int tile = blockIdx.x; tile < NB; tile += gridDim.x) {
        int base = tile * 128;
        // stage concat input (pre-packed fp16) + cp.async h0
        for (int i = t; i < 128 * 8; i += 1024) {
            int node = i >> 3, q = i & 7;
            int n = base + node;
            uint4 v1 = make_uint4(0u, 0u, 0u, 0u), v2 = v1;
            if (n < NN) {
                v1 = *(const uint4*)(g_x1h + n * HH + q * 8);
                v2 = *(const uint4*)(g_x2h + n * HH + q * 8);
            }
            *(uint4*)(sA + node * WP128 + q * 4)      = v1;
            *(uint4*)(sA + node * WP128 + 32 + q * 4) = v2;
        }
        for (int i = t; i < 128 * 8; i += 1024) {
            int row = i >> 3, ch = i & 7;
            int n = base + row;
            if (n < NN)
                CP_ASYNC16(sH0_b + (row * WH0 + ch * 4) * 4,
                           (const char*)(g_h0h + n * HH) + ch * 16);
        }
        CP_COMMIT();
        __syncthreads();

        // phase 1: gg = [x1|x2] @ Wc^T + bc  (K=128)
        {
            float4 acc[2] = {};
#pragma unroll
            for (int s = 0; s < 8; s++) {
                int ko = s * 8;
                uint32_t a0 = sA[(r0 + g) * WP128 + ko + tig];
                uint32_t a1 = sA[(r0 + g + 8) * WP128 + ko + tig];
                uint32_t a2 = sA[(r0 + g) * WP128 + ko + tig + 4];
                uint32_t a3 = sA[(r0 + g + 8) * WP128 + ko + tig + 4];
#pragma unroll
                for (int nt = 0; nt < 2; nt++) {
                    int o = cb + nt * 8 + g;
                    mma16(acc[nt], a0, a1, a2, a3,
                          sWc[o * WP128 + ko + tig], sWc[o * WP128 + ko + tig + 4]);
                }
            }
#pragma unroll
            for (int nt = 0; nt < 2; nt++) {
                int c = cb + nt * 8 + tig * 2;
                int cwd = c >> 1;
                sG[(r0 + g) * WP64 + cwd] =
                    f2h2(acc[nt].x + sbc[c], acc[nt].y + sbc[c + 1]);
                sG[(r0 + g + 8) * WP64 + cwd] =
                    f2h2(acc[nt].z + sbc[c], acc[nt].w + sbc[c + 1]);
            }
        }
        CP_WAIT0();
        __syncthreads();

        // phase 0: ghh = h0 @ Whh^T + bhh  (in-kernel, 48 cols per col group)
        {
            int cbh = cw * 48;
            float4 agh[6] = {};
#pragma unroll
            for (int s = 0; s < 4; s++) {
                int ko = s * 8;
                uint32_t a0 = sH0[(r0 + g) * WH0 + ko + tig];
                uint32_t a1 = sH0[(r0 + g + 8) * WH0 + ko + tig];
                uint32_t a2 = sH0[(r0 + g) * WH0 + ko + tig + 4];
                uint32_t a3 = sH0[(r0 + g + 8) * WH0 + ko + tig + 4];
#pragma unroll
                for (int nt = 0; nt < 6; nt++) {
                    int o = cbh + nt * 8 + g;
                    mma16(agh[nt], a0, a1, a2, a3,
                          sWhh[o * WP64 + ko + tig], sWhh[o * WP64 + ko + tig + 4]);
                }
            }
#pragma unroll
            for (int nt = 0; nt < 6; nt++) {
                int c = cbh + nt * 8 + tig * 2;
                int cwd = c >> 1;
                sGH[(r0 + g) * WGH + cwd] =
                    f2h2(agh[nt].x + sbhh[c], agh[nt].y + sbhh[c + 1]);
                sGH[(r0 + g + 8) * WGH + cwd] =
                    f2h2(agh[nt].z + sbhh[c], agh[nt].w + sbhh[c + 1]);
            }
        }

        // phase 2: gi = gg @ Wih^T
        float4 d2[3][2];
#pragma unroll
        for (int gt = 0; gt < 3; gt++)
#pragma unroll
            for (int nt = 0; nt < 2; nt++)
                d2[gt][nt] = make_float4(0.f, 0.f, 0.f, 0.f);
#pragma unroll
        for (int s = 0; s < 4; s++) {
            int ko = s * 8;
            uint32_t a0 = sG[(r0 + g) * WP64 + ko + tig];
            uint32_t a1 = sG[(r0 + g + 8) * WP64 + ko + tig];
            uint32_t a2 = sG[(r0 + g) * WP64 + ko + tig + 4];
            uint32_t a3 = sG[(r0 + g + 8) * WP64 + ko + tig + 4];
#pragma unroll
            for (int gt = 0; gt < 3; gt++)
#pragma unroll
                for (int nt = 0; nt < 2; nt++) {
                    int o = gt * 64 + cb + nt * 8 + g;
                    mma16(d2[gt][nt], a0, a1, a2, a3,
                          sWih[o * WP64 + ko + tig], sWih[o * WP64 + ko + tig + 4]);
                }
        }
        __syncthreads();   // sGH (cross-warp) must be visible for GRU

        // phase 3: GRU
        float hn[2][4];
#pragma unroll
        for (int nt = 0; nt < 2; nt++) {
            int c = cb + nt * 8 + tig * 2;
            int cwd = c >> 1;
#pragma unroll
            for (int half = 0; half < 2; half++) {
                int nl = r0 + g + half * 8;
                float vr0 = half ? d2[0][nt].z : d2[0][nt].x;
                float vr1 = half ? d2[0][nt].w : d2[0][nt].y;
                float vz0 = half ? d2[1][nt].z : d2[1][nt].x;
                float vz1 = half ? d2[1][nt].w : d2[1][nt].y;
                float vn0 = half ? d2[2][nt].z : d2[2][nt].x;
                float vn1 = half ? d2[2][nt].w : d2[2][nt].y;
                float2 gr = h2f2(sGH[nl * WGH + cwd]);
                float2 gz = h2f2(sGH[nl * WGH + 32 + cwd]);
                float2 gn = h2f2(sGH[nl * WGH + 64 + cwd]);
                float2 h  = h2f2(sH0[nl * WH0 + cwd]);
                float r = sigf(vr0 + sbih[c] + gr.x);
                float z = sigf(vz0 + sbih[64 + c] + gz.x);
                float n = tanhf(vn0 + sbih[128 + c] + r * gn.x);
                hn[nt][half * 2] = (1.f - z) * n + z * h.x;
                r = sigf(vr1 + sbih[c + 1] + gr.y);
                z = sigf(vz1 + sbih[64 + c + 1] + gz.y);
                n = tanhf(vn1 + sbih[128 + c + 1] + r * gn.y);
                hn[nt][half * 2 + 1] = (1.f - z) * n + z * h.y;
            }
        }
        __syncthreads();
#pragma unroll
        for (int nt = 0; nt < 2; nt++) {
            int c = cb + nt * 8 + tig * 2;
            int cwd = c >> 1;
            sG[(r0 + g) * WP64 + cwd]     = f2h2(hn[nt][0], hn[nt][1]);
            sG[(r0 + g + 8) * WP64 + cwd] = f2h2(hn[nt][2], hn[nt][3]);
        }
        __syncthreads();

        // phase 4: output GEMM
        if (!FINAL) {
            float4 acc[2] = {};
#pragma unroll
            for (int s = 0; s < 4; s++) {
                int ko = s * 8;
                uint32_t a0 = sG[(r0 + g) * WP64 + ko + tig];
                uint32_t a1 = sG[(r0 + g + 8) * WP64 + ko + tig];
                uint32_t a2 = sG[(r0 + g) * WP64 + ko + tig + 4];
                uint32_t a3 = sG[(r0 + g + 8) * WP64 + ko + tig + 4];
#pragma unroll
                for (int nt = 0; nt < 2; nt++) {
                    int o = cb + nt * 8 + g;
                    mma16(acc[nt], a0, a1, a2, a3,
                          sWl[o * WP64 + ko + tig], sWl[o * WP64 + ko + tig + 4]);
                }
            }
#pragma unroll
            for (int nt = 0; nt < 2; nt++) {
                int c = cb + nt * 8 + tig * 2;
                int n1 = base + r0 + g, n2 = n1 + 8;
                if (n1 < NN)
                    *(uint32_t*)(g_xmidh + n1 * HH + c) =
                        f2h2(acc[nt].x + sbl[c], acc[nt].y + sbl[c + 1]);
                if (n2 < NN)
                    *(uint32_t*)(g_xmidh + n2 * HH + c) =
                        f2h2(acc[nt].z + sbl[c], acc[nt].w + sbl[c + 1]);
            }
        } else {
            if (cw < 2) {
                float4 acc = make_float4(0.f, 0.f, 0.f, 0.f);
                int c0f = cw * 8;
#pragma unroll
                for (int s = 0; s < 4; s++) {
                    int ko = s * 8;
                    uint32_t a0 = sG[(r0 + g) * WP64 + ko + tig];
                    uint32_t a1 = sG[(r0 + g + 8) * WP64 + ko + tig];
                    uint32_t a2 = sG[(r0 + g) * WP64 + ko + tig + 4];
                    uint32_t a3 = sG[(r0 + g + 8) * WP64 + ko + tig + 4];
                    int o = c0f + g;
                    mma16(acc, a0, a1, a2, a3,
                          sWl[o * WP64 + ko + tig], sWl[o * WP64 + ko + tig + 4]);
                }
                int c = c0f + tig * 2;
                sLY[(r0 + g) * 17 + c]         = acc.x + sbl[c];
                sLY[(r0 + g) * 17 + c + 1]     = acc.y + sbl[c + 1];
                sLY[(r0 + g + 8) * 17 + c]     = acc.z + sbl[c];
                sLY[(r0 + g + 8) * 17 + c + 1] = acc.w + sbl[c + 1];
            }
            __syncthreads();
            if (t < 128) {
                int node = base + t;
                if (node < NN) {
                    float m = -1e30f;
#pragma unroll
                    for (int cc = 0; cc < 16; cc++) m = fmaxf(m, sLY[t * 17 + cc]);
                    float s = 0.f;
#pragma unroll
                    for (int cc = 0; cc < 16; cc++) s += expf(sLY[t * 17 + cc] - m);
                    float l = m + logf(s);
#pragma unroll
                    for (int cc = 0; cc < 16; cc++)
                        dout[node * CC + cc] = sLY[t * 17 + cc] - l;
                }
            }
        }
        __syncthreads();
    }
}

// ---------------- launch -----------------------------------------------------
extern "C" void kernel_launch(void* const* d_in, const int* in_sizes, int n_in,
                              void* d_out, int out_size) {
    const float* x       = (const float*)d_in[0];
    const int*   ei      = (const int*)  d_in[1];
    const float* ew      = (const float*)d_in[2];
    const int*   eir     = (const int*)  d_in[3];
    const float* ewr     = (const float*)d_in[4];
    const float* W_first = (const float*)d_in[5];
    const float* b_first = (const float*)d_in[6];
    const float* W_con1  = (const float*)d_in[7];
    const float* b_con1  = (const float*)d_in[8];
    const float* W_con2  = (const float*)d_in[9];
    const float* b_con2  = (const float*)d_in[10];
    const float* W_lin1  = (const float*)d_in[11];
    const float* b_lin1  = (const float*)d_in[12];
    const float* W_out   = (const float*)d_in[13];
    const float* b_out   = (const float*)d_in[14];
    const float* W_ih    = (const float*)d_in[15];
    const float* W_hh    = (const float*)d_in[16];
    const float* b_ih    = (const float*)d_in[17];
    const float* b_hh    = (const float*)d_in[18];
    float* out = (float*)d_out;

    const int SM_F  = F_WORDS * 4;
    const int SM_CG = CG_WORDS * 4;

    static cudaStream_t s1 = nullptr;
    static cudaEvent_t evFork = nullptr, evS = nullptr;
    if (!s1) {
        cudaStreamCreateWithFlags(&s1, cudaStreamNonBlocking);
        cudaEventCreateWithFlags(&evFork, cudaEventDisableTiming);
        cudaEventCreateWithFlags(&evS, cudaEventDisableTiming);
        cudaFuncSetAttribute(k_first,
                             cudaFuncAttributeMaxDynamicSharedMemorySize, SM_F);
        cudaFuncSetAttribute(k_congru<false>,
                             cudaFuncAttributeMaxDynamicSharedMemorySize, SM_CG);
        cudaFuncSetAttribute(k_congru<true>,
                             cudaFuncAttributeMaxDynamicSharedMemorySize, SM_CG);
    }

    const int PERS = 148;
    const int PROP_BLOCKS = (2 * NN) / 16;   // 12500: 16 dst-nodes per CTA

    // fork: s1 builds the CSR (independent of k_first)
    cudaEventRecord(evFork, 0);
    cudaStreamWaitEvent(s1, evFork, 0);
    k_zcnt<<<(NN + 255) / 256, 256, 0, s1>>>();
    k_hist<<<(EE + 255) / 256, 256, 0, s1>>>(ei, eir);
    k_psum<<<2 * NCH, 1024, 0, s1>>>();
    k_topscan<<<1, 256, 0, s1>>>();
    k_makeoff<<<2 * NCH, 1024, 0, s1>>>();
    k_scatter<<<(EE + 255) / 256, 256, 0, s1>>>(ei, ew, eir, ewr);
    cudaEventRecord(evS, s1);

    // main: k_first (concurrent with CSR build), then the serial chain
    k_first<<<PERS, 1024, SM_F>>>(x, W_first, b_first);
    cudaStreamWaitEvent(0, evS, 0);
    k_prop_csr<<<PROP_BLOCKS, 256>>>(0);
    k_congru<false><<<PERS, 1024, SM_CG>>>(W_con1, b_con1, W_ih, b_ih,
                                           W_hh, b_hh, W_lin1, b_lin1, nullptr);
    k_prop_csr<<<PROP_BLOCKS, 256>>>(1);
    k_congru<true><<<PERS, 1024, SM_CG>>>(W_con2, b_con2, W_ih, b_ih,
                                          W_hh, b_hh, W_out, b_out, out);
}

// round 17
// speedup vs baseline: 1.4899x; 1.0814x over previous
#include <cuda_runtime.h>
#include <cuda_fp16.h>
#include <math.h>
#include <stdint.h>

#define NN 100000
#define FF 128
#define HH 64
#define CC 16
#define EE 1000000
#define NB 782   // ceil(NN/128)
#define NCH 98   // ceil(NN/1024)
#define CHK 1024

// word strides (uint32 units)
#define WP128 68
#define WP64  36
#define WGH  100
#define WH0   36

// ---------------- scratch ----------------------------------------------------
__device__ __align__(16) __half g_h0h[NN * HH];
__device__ __align__(16) __half g_xmidh[NN * HH];
__device__ __align__(16) __half g_x1h[NN * HH];
__device__ __align__(16) __half g_x2h[NN * HH];

// CSR build scratch
__device__ int g_cnt1[NN], g_cnt2[NN];
__device__ int g_off1[NN + 1], g_off2[NN + 1];
__device__ int g_pos1[NN], g_pos2[NN];
__device__ int g_psum[2 * NCH];
__device__ __align__(8) int2 g_se1[EE];
__device__ __align__(8) int2 g_se2[EE];

// ---------------- helpers -----------------------------------------------------
__device__ __forceinline__ uint32_t f2h2(float a, float b) {
    __half2 h = __floats2half2_rn(a, b);
    return *(uint32_t*)&h;
}
__device__ __forceinline__ float2 h2f2(uint32_t u) {
    return __half22float2(*(__half2*)&u);
}
__device__ __forceinline__ void mma16(float4& d, uint32_t a0, uint32_t a1,
                                      uint32_t a2, uint32_t a3,
                                      uint32_t b0, uint32_t b1) {
    asm volatile(
        "mma.sync.aligned.m16n8k16.row.col.f32.f16.f16.f32 "
        "{%0,%1,%2,%3},{%4,%5,%6,%7},{%8,%9},{%0,%1,%2,%3};"
        : "+f"(d.x), "+f"(d.y), "+f"(d.z), "+f"(d.w)
        : "r"(a0), "r"(a1), "r"(a2), "r"(a3), "r"(b0), "r"(b1));
}
__device__ __forceinline__ float sigf(float x) {
    return 1.f / (1.f + __expf(-x));
}
__device__ __forceinline__ uint32_t smem_u32(const void* p) {
    uint32_t a;
    asm("{ .reg .u64 t; cvta.to.shared.u64 t, %1; cvt.u32.u64 %0, t; }"
        : "=r"(a) : "l"(p));
    return a;
}
#define CP_ASYNC16(dst, src) \
    asm volatile("cp.async.cg.shared.global [%0], [%1], 16;" \
                 :: "r"(dst), "l"(src) : "memory")
#define CP_COMMIT() asm volatile("cp.async.commit_group;" ::: "memory")
#define CP_WAIT0()  asm volatile("cp.async.wait_group 0;" ::: "memory")

// ================= CSR build ==================================================
__global__ void k_zcnt() {
    int i = blockIdx.x * blockDim.x + threadIdx.x;
    if (i < NN) { g_cnt1[i] = 0; g_cnt2[i] = 0; }
}
__global__ void k_hist(const int* __restrict__ ei1,
                       const int* __restrict__ ei2) {
    int e = blockIdx.x * blockDim.x + threadIdx.x;
    if (e < EE) {
        atomicAdd(&g_cnt1[ei1[EE + e]], 1);
        atomicAdd(&g_cnt2[ei2[EE + e]], 1);
    }
}
__global__ __launch_bounds__(1024) void k_psum() {
    int b = blockIdx.x, t = threadIdx.x;
    const int* cnt = (b < NCH) ? g_cnt1 : g_cnt2;
    int ch = (b < NCH) ? b : b - NCH;
    int n = ch * CHK + t;
    int v = (n < NN) ? cnt[n] : 0;
    __shared__ int ss[1024];
    ss[t] = v; __syncthreads();
    for (int d = 512; d > 0; d >>= 1) {
        if (t < d) ss[t] += ss[t + d];
        __syncthreads();
    }
    if (t == 0) g_psum[b] = ss[0];
}
__global__ __launch_bounds__(256) void k_topscan() {
    __shared__ int s[2 * NCH];
    int t = threadIdx.x;
    if (t < 2 * NCH) s[t] = g_psum[t];
    __syncthreads();
    if (t == 0) { int a = 0; for (int i = 0; i < NCH; i++) { int v = s[i]; s[i] = a; a += v; } }
    if (t == 1) { int a = 0; for (int i = NCH; i < 2 * NCH; i++) { int v = s[i]; s[i] = a; a += v; } }
    __syncthreads();
    if (t < 2 * NCH) g_psum[t] = s[t];
}
__global__ __launch_bounds__(1024) void k_makeoff() {
    int b = blockIdx.x, t = threadIdx.x;
    bool l1 = (b < NCH);
    const int* cnt = l1 ? g_cnt1 : g_cnt2;
    int* off = l1 ? g_off1 : g_off2;
    int* pos = l1 ? g_pos1 : g_pos2;
    int ch = l1 ? b : b - NCH;
    int n = ch * CHK + t;
    int v = (n < NN) ? cnt[n] : 0;
    __shared__ int ss[1024];
    ss[t] = v; __syncthreads();
    for (int d = 1; d < 1024; d <<= 1) {
        int x = (t >= d) ? ss[t - d] : 0;
        __syncthreads();
        ss[t] += x;
        __syncthreads();
    }
    int excl = ss[t] - v + g_psum[b];
    if (n < NN) { off[n] = excl; pos[n] = excl; }
    if (t == 0 && ch == NCH - 1) off[NN] = EE;
}
__global__ void k_scatter(const int* __restrict__ ei1,
                          const float* __restrict__ ew1,
                          const int* __restrict__ ei2,
                          const float* __restrict__ ew2) {
    int e = blockIdx.x * blockDim.x + threadIdx.x;
    if (e < EE) {
        int d1 = ei1[EE + e];
        int p1 = atomicAdd(&g_pos1[d1], 1);
        g_se1[p1] = make_int2(ei1[e], __float_as_int(ew1[e]));
        int d2 = ei2[EE + e];
        int p2 = atomicAdd(&g_pos2[d2], 1);
        g_se2[p2] = make_int2(ei2[e], __float_as_int(ew2[e]));
    }
}

// ---------------- gather-CSR propagation: 8 lanes per dst node ---------------
// Each thread owns 16B (8 halves) of its node's row; uint4 gather loads,
// fp32 register accumulation, single fp16 rounding at the uint4 store.
__global__ __launch_bounds__(256) void k_prop_csr(int use_mid) {
    const __half* xin = use_mid ? g_xmidh : g_h0h;
    int gi = blockIdx.x * 32 + (threadIdx.x >> 3);
    int gl = threadIdx.x & 7;

    const int* off; const int2* se; __half* out; int node;
    if (gi < NN) { node = gi;      off = g_off1; se = g_se1; out = g_x1h; }
    else         { node = gi - NN; off = g_off2; se = g_se2; out = g_x2h; }

    float a0 = 0.f, a1 = 0.f, a2 = 0.f, a3 = 0.f;
    float a4 = 0.f, a5 = 0.f, a6 = 0.f, a7 = 0.f;
    int e = off[node], end = off[node + 1];
    for (; e + 1 < end; e += 2) {
        int2 ed0 = __ldg(&se[e]);
        int2 ed1 = __ldg(&se[e + 1]);
        uint4 u0 = *(const uint4*)(xin + ed0.x * HH + gl * 8);
        uint4 u1 = *(const uint4*)(xin + ed1.x * HH + gl * 8);
        float w0 = __int_as_float(ed0.y), w1 = __int_as_float(ed1.y);
        float2 p;
        p = h2f2(u0.x); a0 += p.x * w0; a1 += p.y * w0;
        p = h2f2(u0.y); a2 += p.x * w0; a3 += p.y * w0;
        p = h2f2(u0.z); a4 += p.x * w0; a5 += p.y * w0;
        p = h2f2(u0.w); a6 += p.x * w0; a7 += p.y * w0;
        p = h2f2(u1.x); a0 += p.x * w1; a1 += p.y * w1;
        p = h2f2(u1.y); a2 += p.x * w1; a3 += p.y * w1;
        p = h2f2(u1.z); a4 += p.x * w1; a5 += p.y * w1;
        p = h2f2(u1.w); a6 += p.x * w1; a7 += p.y * w1;
    }
    if (e < end) {
        int2 ed0 = __ldg(&se[e]);
        uint4 u0 = *(const uint4*)(xin + ed0.x * HH + gl * 8);
        float w0 = __int_as_float(ed0.y);
        float2 p;
        p = h2f2(u0.x); a0 += p.x * w0; a1 += p.y * w0;
        p = h2f2(u0.y); a2 += p.x * w0; a3 += p.y * w0;
        p = h2f2(u0.z); a4 += p.x * w0; a5 += p.y * w0;
        p = h2f2(u0.w); a6 += p.x * w0; a7 += p.y * w0;
    }
    uint4 pk;
    pk.x = f2h2(a0, a1); pk.y = f2h2(a2, a3);
    pk.z = f2h2(a4, a5); pk.w = f2h2(a6, a7);
    *(uint4*)(out + node * HH + gl * 8) = pk;
}

// ---------------- persistent k_first: h0 = x@Wf^T+bf -------------------------
#define F_A    0
#define F_WF   (F_A + 128 * WP128)
#define F_WORDS (F_WF + 64 * WP128)

__global__ __launch_bounds__(1024, 1) void k_first(const float* __restrict__ x,
                                                   const float* __restrict__ Wf,
                                                   const float* __restrict__ bf) {
    extern __shared__ uint32_t sm[];
    uint32_t* sA  = sm + F_A;
    uint32_t* sWf = sm + F_WF;
    __shared__ float sbf[64];
    int t = threadIdx.x;

    for (int i = t; i < 64 * 32; i += 1024) {
        int o = i >> 5, q = i & 31;
        float4 v = *(const float4*)(Wf + o * FF + q * 4);
        sWf[o * WP128 + q * 2]     = f2h2(v.x, v.y);
        sWf[o * WP128 + q * 2 + 1] = f2h2(v.z, v.w);
    }
    if (t < 64) sbf[t] = bf[t];
    __syncthreads();

    int w = t >> 5, lane = t & 31, g = lane >> 2, tig = lane & 3;
    int r0 = (w & 7) * 16, cw = w >> 3;

    for (int tile = blockIdx.x; tile < NB; tile += gridDim.x) {
        int base = tile * 128;
        for (int i = t; i < 128 * 32; i += 1024) {
            int node = i >> 5, q = i & 31;
            float4 v = make_float4(0.f, 0.f, 0.f, 0.f);
            if (base + node < NN)
                v = *(const float4*)(x + (base + node) * FF + q * 4);
            sA[node * WP128 + q * 2]     = f2h2(v.x, v.y);
            sA[node * WP128 + q * 2 + 1] = f2h2(v.z, v.w);
        }
        __syncthreads();

        int cb = cw * 16;
        float4 acc[2] = {};
#pragma unroll
        for (int s = 0; s < 8; s++) {
            int ko = s * 8;
            uint32_t a0 = sA[(r0 + g) * WP128 + ko + tig];
            uint32_t a1 = sA[(r0 + g + 8) * WP128 + ko + tig];
            uint32_t a2 = sA[(r0 + g) * WP128 + ko + tig + 4];
            uint32_t a3 = sA[(r0 + g + 8) * WP128 + ko + tig + 4];
#pragma unroll
            for (int nt = 0; nt < 2; nt++) {
                int o = cb + nt * 8 + g;
                mma16(acc[nt], a0, a1, a2, a3,
                      sWf[o * WP128 + ko + tig], sWf[o * WP128 + ko + tig + 4]);
            }
        }
#pragma unroll
        for (int nt = 0; nt < 2; nt++) {
            int c = cb + nt * 8 + tig * 2;
            int n1 = base + r0 + g, n2 = n1 + 8;
            if (n1 < NN)
                *(uint32_t*)(g_h0h + n1 * HH + c) =
                    f2h2(acc[nt].x + sbf[c], acc[nt].y + sbf[c + 1]);
            if (n2 < NN)
                *(uint32_t*)(g_h0h + n2 * HH + c) =
                    f2h2(acc[nt].z + sbf[c], acc[nt].w + sbf[c + 1]);
        }
        __syncthreads();
    }
}

// ---------------- persistent fused: ghh-in-kernel + concat + GRU + out -------
#define O_A    0
#define O_WC   (O_A + 128 * WP128)
#define O_WIH  (O_WC + 64 * WP128)
#define O_WHH  (O_WIH + 192 * WP64)
#define O_WL   (O_WHH + 192 * WP64)
#define O_G    (O_WL + 64 * WP64)
#define O_GH   (O_G + 128 * WP64)
#define O_H0   (O_GH + 128 * WGH)
#define O_BC   (O_H0 + 128 * WH0)
#define O_BIH  (O_BC + 64)
#define O_BHH  (O_BIH + 192)
#define O_BL   (O_BHH + 192)
#define O_LY   (O_BL + 64)
#define CG_WORDS (O_LY + 128 * 17)

template <bool FINAL>
__global__ __launch_bounds__(1024, 1) void k_congru(
    const float* __restrict__ Wc,  const float* __restrict__ bc,
    const float* __restrict__ Wih, const float* __restrict__ bih,
    const float* __restrict__ Whh, const float* __restrict__ bhh,
    const float* __restrict__ Wl,  const float* __restrict__ bl,
    float* __restrict__ dout) {
    extern __shared__ uint32_t sm[];
    uint32_t* sA   = sm + O_A;
    uint32_t* sWc  = sm + O_WC;
    uint32_t* sWih = sm + O_WIH;
    uint32_t* sWhh = sm + O_WHH;
    uint32_t* sWl  = sm + O_WL;
    uint32_t* sG   = sm + O_G;
    uint32_t* sGH  = sm + O_GH;
    uint32_t* sH0  = sm + O_H0;
    float* sbc  = (float*)(sm + O_BC);
    float* sbih = (float*)(sm + O_BIH);
    float* sbhh = (float*)(sm + O_BHH);
    float* sbl  = (float*)(sm + O_BL);
    float* sLY  = (float*)(sm + O_LY);
    const int OC = FINAL ? CC : HH;

    int t = threadIdx.x;
    uint32_t sH0_b = smem_u32(sH0);

    for (int i = t; i < 64 * 32; i += 1024) {
        int o = i >> 5, q = i & 31;
        float4 v = *(const float4*)(Wc + o * FF + q * 4);
        sWc[o * WP128 + q * 2]     = f2h2(v.x, v.y);
        sWc[o * WP128 + q * 2 + 1] = f2h2(v.z, v.w);
    }
    for (int i = t; i < 192 * 16; i += 1024) {
        int o = i >> 4, q = i & 15;
        float4 v = *(const float4*)(Wih + o * HH + q * 4);
        sWih[o * WP64 + q * 2]     = f2h2(v.x, v.y);
        sWih[o * WP64 + q * 2 + 1] = f2h2(v.z, v.w);
        float4 u = *(const float4*)(Whh + o * HH + q * 4);
        sWhh[o * WP64 + q * 2]     = f2h2(u.x, u.y);
        sWhh[o * WP64 + q * 2 + 1] = f2h2(u.z, u.w);
    }
    for (int i = t; i < OC * 16; i += 1024) {
        int o = i >> 4, q = i & 15;
        float4 v = *(const float4*)(Wl + o * HH + q * 4);
        sWl[o * WP64 + q * 2]     = f2h2(v.x, v.y);
        sWl[o * WP64 + q * 2 + 1] = f2h2(v.z, v.w);
    }
    if (t < 64)  sbc[t]  = bc[t];
    if (t < 192) sbih[t] = bih[t];
    if (t >= 256 && t < 448) sbhh[t - 256] = bhh[t - 256];
    if (t >= 512 && t < 512 + OC) sbl[t - 512] = bl[t - 512];
    __syncthreads();

    int w = t >> 5, lane = t & 31, g = lane >> 2, tig = lane & 3;
    int r0 = (w & 7) * 16, cw = w >> 3, cb = cw * 16;

    for (int tile = blockIdx.x; tile < NB; tile += gridDim.x) {
        int base = tile * 128;
        // stage concat input (pre-packed fp16) + cp.async h0
        for (int i = t; i < 128 * 8; i += 1024) {
            int node = i >> 3, q = i & 7;
            int n = base + node;
            uint4 v1 = make_uint4(0u, 0u, 0u, 0u), v2 = v1;
            if (n < NN) {
                v1 = *(const uint4*)(g_x1h + n * HH + q * 8);
                v2 = *(const uint4*)(g_x2h + n * HH + q * 8);
            }
            *(uint4*)(sA + node * WP128 + q * 4)      = v1;
            *(uint4*)(sA + node * WP128 + 32 + q * 4) = v2;
        }
        for (int i = t; i < 128 * 8; i += 1024) {
            int row = i >> 3, ch = i & 7;
            int n = base + row;
            if (n < NN)
                CP_ASYNC16(sH0_b + (row * WH0 + ch * 4) * 4,
                           (const char*)(g_h0h + n * HH) + ch * 16);
        }
        CP_COMMIT();
        __syncthreads();

        // phase 1: gg = [x1|x2] @ Wc^T + bc  (K=128)
        {
            float4 acc[2] = {};
#pragma unroll
            for (int s = 0; s < 8; s++) {
                int ko = s * 8;
                uint32_t a0 = sA[(r0 + g) * WP128 + ko + tig];
                uint32_t a1 = sA[(r0 + g + 8) * WP128 + ko + tig];
                uint32_t a2 = sA[(r0 + g) * WP128 + ko + tig + 4];
                uint32_t a3 = sA[(r0 + g + 8) * WP128 + ko + tig + 4];
#pragma unroll
                for (int nt = 0; nt < 2; nt++) {
                    int o = cb + nt * 8 + g;
                    mma16(acc[nt], a0, a1, a2, a3,
                          sWc[o * WP128 + ko + tig], sWc[o * WP128 + ko + tig + 4]);
                }
            }
#pragma unroll
            for (int nt = 0; nt < 2; nt++) {
                int c = cb + nt * 8 + tig * 2;
                int cwd = c >> 1;
                sG[(r0 + g) * WP64 + cwd] =
                    f2h2(acc[nt].x + sbc[c], acc[nt].y + sbc[c + 1]);
                sG[(r0 + g + 8) * WP64 + cwd] =
                    f2h2(acc[nt].z + sbc[c], acc[nt].w + sbc[c + 1]);
            }
        }
        CP_WAIT0();
        __syncthreads();

        // phase 0: ghh = h0 @ Whh^T + bhh  (in-kernel)
        {
            int cbh = cw * 48;
            float4 agh[6] = {};
#pragma unroll
            for (int s = 0; s < 4; s++) {
                int ko = s * 8;
                uint32_t a0 = sH0[(r0 + g) * WH0 + ko + tig];
                uint32_t a1 = sH0[(r0 + g + 8) * WH0 + ko + tig];
                uint32_t a2 = sH0[(r0 + g) * WH0 + ko + tig + 4];
                uint32_t a3 = sH0[(r0 + g + 8) * WH0 + ko + tig + 4];
#pragma unroll
                for (int nt = 0; nt < 6; nt++) {
                    int o = cbh + nt * 8 + g;
                    mma16(agh[nt], a0, a1, a2, a3,
                          sWhh[o * WP64 + ko + tig], sWhh[o * WP64 + ko + tig + 4]);
                }
            }
#pragma unroll
            for (int nt = 0; nt < 6; nt++) {
                int c = cbh + nt * 8 + tig * 2;
                int cwd = c >> 1;
                sGH[(r0 + g) * WGH + cwd] =
                    f2h2(agh[nt].x + sbhh[c], agh[nt].y + sbhh[c + 1]);
                sGH[(r0 + g + 8) * WGH + cwd] =
                    f2h2(agh[nt].z + sbhh[c], agh[nt].w + sbhh[c + 1]);
            }
        }

        // phase 2: gi = gg @ Wih^T
        float4 d2[3][2];
#pragma unroll
        for (int gt = 0; gt < 3; gt++)
#pragma unroll
            for (int nt = 0; nt < 2; nt++)
                d2[gt][nt] = make_float4(0.f, 0.f, 0.f, 0.f);
#pragma unroll
        for (int s = 0; s < 4; s++) {
            int ko = s * 8;
            uint32_t a0 = sG[(r0 + g) * WP64 + ko + tig];
            uint32_t a1 = sG[(r0 + g + 8) * WP64 + ko + tig];
            uint32_t a2 = sG[(r0 + g) * WP64 + ko + tig + 4];
            uint32_t a3 = sG[(r0 + g + 8) * WP64 + ko + tig + 4];
#pragma unroll
            for (int gt = 0; gt < 3; gt++)
#pragma unroll
                for (int nt = 0; nt < 2; nt++) {
                    int o = gt * 64 + cb + nt * 8 + g;
                    mma16(d2[gt][nt], a0, a1, a2, a3,
                          sWih[o * WP64 + ko + tig], sWih[o * WP64 + ko + tig + 4]);
                }
        }
        __syncthreads();   // sGH visible for GRU

        // phase 3: GRU
        float hn[2][4];
#pragma unroll
        for (int nt = 0; nt < 2; nt++) {
            int c = cb + nt * 8 + tig * 2;
            int cwd = c >> 1;
#pragma unroll
            for (int half = 0; half < 2; half++) {
                int nl = r0 + g + half * 8;
                float vr0 = half ? d2[0][nt].z : d2[0][nt].x;
                float vr1 = half ? d2[0][nt].w : d2[0][nt].y;
                float vz0 = half ? d2[1][nt].z : d2[1][nt].x;
                float vz1 = half ? d2[1][nt].w : d2[1][nt].y;
                float vn0 = half ? d2[2][nt].z : d2[2][nt].x;
                float vn1 = half ? d2[2][nt].w : d2[2][nt].y;
                float2 gr = h2f2(sGH[nl * WGH + cwd]);
                float2 gz = h2f2(sGH[nl * WGH + 32 + cwd]);
                float2 gn2 = h2f2(sGH[nl * WGH + 64 + cwd]);
                float2 h  = h2f2(sH0[nl * WH0 + cwd]);
                float r = sigf(vr0 + sbih[c] + gr.x);
                float z = sigf(vz0 + sbih[64 + c] + gz.x);
                float n = tanhf(vn0 + sbih[128 + c] + r * gn2.x);
                hn[nt][half * 2] = (1.f - z) * n + z * h.x;
                r = sigf(vr1 + sbih[c + 1] + gr.y);
                z = sigf(vz1 + sbih[64 + c + 1] + gz.y);
                n = tanhf(vn1 + sbih[128 + c + 1] + r * gn2.y);
                hn[nt][half * 2 + 1] = (1.f - z) * n + z * h.y;
            }
        }
        __syncthreads();
#pragma unroll
        for (int nt = 0; nt < 2; nt++) {
            int c = cb + nt * 8 + tig * 2;
            int cwd = c >> 1;
            sG[(r0 + g) * WP64 + cwd]     = f2h2(hn[nt][0], hn[nt][1]);
            sG[(r0 + g + 8) * WP64 + cwd] = f2h2(hn[nt][2], hn[nt][3]);
        }
        __syncthreads();

        // phase 4: output GEMM
        if (!FINAL) {
            float4 acc[2] = {};
#pragma unroll
            for (int s = 0; s < 4; s++) {
                int ko = s * 8;
                uint32_t a0 = sG[(r0 + g) * WP64 + ko + tig];
                uint32_t a1 = sG[(r0 + g + 8) * WP64 + ko + tig];
                uint32_t a2 = sG[(r0 + g) * WP64 + ko + tig + 4];
                uint32_t a3 = sG[(r0 + g + 8) * WP64 + ko + tig + 4];
#pragma unroll
                for (int nt = 0; nt < 2; nt++) {
                    int o = cb + nt * 8 + g;
                    mma16(acc[nt], a0, a1, a2, a3,
                          sWl[o * WP64 + ko + tig], sWl[o * WP64 + ko + tig + 4]);
                }
            }
#pragma unroll
            for (int nt = 0; nt < 2; nt++) {
                int c = cb + nt * 8 + tig * 2;
                int n1 = base + r0 + g, n2 = n1 + 8;
                if (n1 < NN)
                    *(uint32_t*)(g_xmidh + n1 * HH + c) =
                        f2h2(acc[nt].x + sbl[c], acc[nt].y + sbl[c + 1]);
                if (n2 < NN)
                    *(uint32_t*)(g_xmidh + n2 * HH + c) =
                        f2h2(acc[nt].z + sbl[c], acc[nt].w + sbl[c + 1]);
            }
        } else {
            if (cw < 2) {
                float4 acc = make_float4(0.f, 0.f, 0.f, 0.f);
                int c0f = cw * 8;
#pragma unroll
                for (int s = 0; s < 4; s++) {
                    int ko = s * 8;
                    uint32_t a0 = sG[(r0 + g) * WP64 + ko + tig];
                    uint32_t a1 = sG[(r0 + g + 8) * WP64 + ko + tig];
                    uint32_t a2 = sG[(r0 + g) * WP64 + ko + tig + 4];
                    uint32_t a3 = sG[(r0 + g + 8) * WP64 + ko + tig + 4];
                    int o = c0f + g;
                    mma16(acc, a0, a1, a2, a3,
                          sWl[o * WP64 + ko + tig], sWl[o * WP64 + ko + tig + 4]);
                }
                int c = c0f + tig * 2;
                sLY[(r0 + g) * 17 + c]         = acc.x + sbl[c];
                sLY[(r0 + g) * 17 + c + 1]     = acc.y + sbl[c + 1];
                sLY[(r0 + g + 8) * 17 + c]     = acc.z + sbl[c];
                sLY[(r0 + g + 8) * 17 + c + 1] = acc.w + sbl[c + 1];
            }
            __syncthreads();
            if (t < 128) {
                int node = base + t;
                if (node < NN) {
                    float m = -1e30f;
#pragma unroll
                    for (int cc = 0; cc < 16; cc++) m = fmaxf(m, sLY[t * 17 + cc]);
                    float s = 0.f;
#pragma unroll
                    for (int cc = 0; cc < 16; cc++) s += expf(sLY[t * 17 + cc] - m);
                    float l = m + logf(s);
#pragma unroll
                    for (int cc = 0; cc < 16; cc++)
                        dout[node * CC + cc] = sLY[t * 17 + cc] - l;
                }
            }
        }
        __syncthreads();
    }
}

// ---------------- launch -----------------------------------------------------
extern "C" void kernel_launch(void* const* d_in, const int* in_sizes, int n_in,
                              void* d_out, int out_size) {
    const float* x       = (const float*)d_in[0];
    const int*   ei      = (const int*)  d_in[1];
    const float* ew      = (const float*)d_in[2];
    const int*   eir     = (const int*)  d_in[3];
    const float* ewr     = (const float*)d_in[4];
    const float* W_first = (const float*)d_in[5];
    const float* b_first = (const float*)d_in[6];
    const float* W_con1  = (const float*)d_in[7];
    const float* b_con1  = (const float*)d_in[8];
    const float* W_con2  = (const float*)d_in[9];
    const float* b_con2  = (const float*)d_in[10];
    const float* W_lin1  = (const float*)d_in[11];
    const float* b_lin1  = (const float*)d_in[12];
    const float* W_out   = (const float*)d_in[13];
    const float* b_out   = (const float*)d_in[14];
    const float* W_ih    = (const float*)d_in[15];
    const float* W_hh    = (const float*)d_in[16];
    const float* b_ih    = (const float*)d_in[17];
    const float* b_hh    = (const float*)d_in[18];
    float* out = (float*)d_out;

    const int SM_F  = F_WORDS * 4;
    const int SM_CG = CG_WORDS * 4;

    static cudaStream_t s1 = nullptr;
    static cudaEvent_t evFork = nullptr, evS = nullptr;
    if (!s1) {
        cudaStreamCreateWithFlags(&s1, cudaStreamNonBlocking);
        cudaEventCreateWithFlags(&evFork, cudaEventDisableTiming);
        cudaEventCreateWithFlags(&evS, cudaEventDisableTiming);
        cudaFuncSetAttribute(k_first,
                             cudaFuncAttributeMaxDynamicSharedMemorySize, SM_F);
        cudaFuncSetAttribute(k_congru<false>,
                             cudaFuncAttributeMaxDynamicSharedMemorySize, SM_CG);
        cudaFuncSetAttribute(k_congru<true>,
                             cudaFuncAttributeMaxDynamicSharedMemorySize, SM_CG);
    }

    const int PERS = 148;
    const int PROP_BLOCKS = (2 * NN + 31) / 32;  // 8 lanes/node, 32 nodes/CTA

    // fork: s1 builds the CSR (independent of k_first)
    cudaEventRecord(evFork, 0);
    cudaStreamWaitEvent(s1, evFork, 0);
    k_zcnt<<<(NN + 255) / 256, 256, 0, s1>>>();
    k_hist<<<(EE + 255) / 256, 256, 0, s1>>>(ei, eir);
    k_psum<<<2 * NCH, 1024, 0, s1>>>();
    k_topscan<<<1, 256, 0, s1>>>();
    k_makeoff<<<2 * NCH, 1024, 0, s1>>>();
    k_scatter<<<(EE + 255) / 256, 256, 0, s1>>>(ei, ew, eir, ewr);
    cudaEventRecord(evS, s1);

    // main: k_first (concurrent with CSR build), then the serial chain
    k_first<<<PERS, 1024, SM_F>>>(x, W_first, b_first);
    cudaStreamWaitEvent(0, evS, 0);
    k_prop_csr<<<PROP_BLOCKS, 256>>>(0);
    k_congru<false><<<PERS, 1024, SM_CG>>>(W_con1, b_con1, W_ih, b_ih,
                                           W_hh, b_hh, W_lin1, b_lin1, nullptr);
    k_prop_csr<<<PROP_BLOCKS, 256>>>(1);
    k_congru<true><<<PERS, 1024, SM_CG>>>(W_con2, b_con2, W_ih, b_ih,
                                          W_hh, b_hh, W_out, b_out, out);
}